// round 3
// baseline (speedup 1.0000x reference)
#include <cuda_runtime.h>
#include <stdint.h>

#define TT   4
#define NN   20000
#define EE   320000
#define FF   64
#define HH   64
#define TSN  50
#define G4H  256      // 4 gates * H
#define KA   192      // agg_x(64) | x_norm(64) | agg_h(64)
#define KSEL 10000    // top-k
#define BK   16

// ---------------- device scratch (static, allocation-free) ----------------
__device__ __align__(16) float g_A[NN * KA];
__device__ __align__(16) float g_h[NN * HH];
__device__ __align__(16) float g_c[NN * HH];
__device__ float g_degacc[NN];
__device__ float g_dinv[NN];
__device__ float g_self[NN];
__device__ float g_gcn[EE];
__device__ int   g_src[EE];
__device__ int   g_dst[EE];
__device__ int   g_is64;
__device__ __align__(16) float g_Wc_hi[KA * G4H];
__device__ __align__(16) float g_Wc_lo[KA * G4H];
__device__ __align__(16) float g_bc[G4H];
__device__ float g_colsum[FF];
__device__ float g_colsq[FF];
__device__ float g_mean[FF];
__device__ float g_rinv[FF];
__device__ float g_v[HH];
__device__ float g_raw[NN];
__device__ float g_sig[NN];
__device__ unsigned g_key[NN];
__device__ float g_high[HH];
__device__ __align__(16) float g_G[TSN * G4H];
__device__ float g_hl[HH];
__device__ unsigned g_hist[256];
__device__ unsigned g_prefix;
__device__ unsigned g_kk;
__device__ unsigned g_ticket;
__device__ unsigned g_cs_ticket, g_h_ticket, g_sc_ticket;
__device__ float g_ssum, g_ssq, g_smean, g_sinv, g_ploss;

__device__ __forceinline__ float sigm(float x) { return 1.f / (1.f + expf(-x)); }

__device__ __forceinline__ unsigned f2tf32(float x) {
    unsigned r;
    asm("cvt.rna.tf32.f32 %0, %1;" : "=r"(r) : "f"(x));
    return r;
}

// split x into tf32 hi + tf32 lo (3xTF32 scheme)
__device__ __forceinline__ void tf32split(float x, float& hi, float& lo) {
    unsigned hb = f2tf32(x);
    float h = __uint_as_float(hb);
    float l = x - h;
    hi = h;
    lo = __uint_as_float(f2tf32(l));
}

#define MMA_TF32(c0, c1, c2, c3, a0, a1, a2, a3, b0, b1)                         \
    asm volatile("mma.sync.aligned.m16n8k8.row.col.f32.tf32.tf32.f32 "           \
                 "{%0,%1,%2,%3}, {%4,%5,%6,%7}, {%8,%9}, {%0,%1,%2,%3};"         \
                 : "+f"(c0), "+f"(c1), "+f"(c2), "+f"(c3)                        \
                 : "r"(a0), "r"(a1), "r"(a2), "r"(a3), "r"(b0), "r"(b1))

// ---------------- edge-index dtype detection + decode + global zero ----------------
__global__ void k_detect(const void* eiraw) {
    if (threadIdx.x == 0) {
        const long long* p = (const long long*)eiraw;
        int ok = 1;
        for (int i = 0; i < 8; i++) {
            long long v = p[i];
            if (v < 0 || v >= NN) ok = 0;
        }
        g_is64 = ok;
    }
}

__global__ void k_decode_zero(const void* eiraw) {
    int i = blockIdx.x * blockDim.x + threadIdx.x;
    if (i < EE) {
        int s, d;
        if (g_is64) {
            const long long* p = (const long long*)eiraw;
            s = (int)p[i];
            d = (int)p[EE + i];
        } else {
            const int* p = (const int*)eiraw;
            s = p[i];
            d = p[EE + i];
        }
        s = min(max(s, 0), NN - 1);
        d = min(max(d, 0), NN - 1);
        g_src[i] = s;
        g_dst[i] = d;
    }
    if (i < NN) g_degacc[i] = 0.f;
    if (i < TSN * G4H) g_G[i] = 0.f;
    if (i < HH) g_high[i] = 0.f;
    if (i < 256) g_hist[i] = 0u;
    if (i < FF) { g_colsum[i] = 0.f; g_colsq[i] = 0.f; }
    if (i == 0) {
        g_prefix = 0u; g_kk = KSEL; g_ticket = 0u;
        g_cs_ticket = 0u; g_h_ticket = 0u; g_sc_ticket = 0u;
        g_ssum = 0.f; g_ssq = 0.f; g_ploss = 0.f;
    }
}

__global__ void k_deg() {
    int e = blockIdx.x * blockDim.x + threadIdx.x;
    if (e < EE) atomicAdd(&g_degacc[g_dst[e]], 1.f);
}

__global__ void k_init_nodes(const float* __restrict__ h0, const float* __restrict__ c0) {
    int i = blockIdx.x * blockDim.x + threadIdx.x;
    if (i < NN) {
        float d = g_degacc[i] + 1.f;
        g_dinv[i] = rsqrtf(d);
        g_self[i] = 1.f / d;
    }
    if (i < NN * HH) { g_h[i] = h0[i]; g_c[i] = c0[i]; }
}

__global__ void k_gcn() {
    int e = blockIdx.x * blockDim.x + threadIdx.x;
    if (e < EE) g_gcn[e] = g_dinv[g_src[e]] * g_dinv[g_dst[e]];
}

__global__ void k_wc(const float* __restrict__ Wrel, const float* __restrict__ brel,
                     const float* __restrict__ Wroot, const float* __restrict__ Wg,
                     const float* __restrict__ bg) {
    int idx = blockIdx.x * blockDim.x + threadIdx.x;
    if (idx < KA * G4H) {
        int k = idx / G4H, col = idx % G4H;
        int g = col >> 6, h2 = col & 63;
        float w;
        if (k < 64)       w = Wrel [g * 4096 + k * 64 + h2];
        else if (k < 128) w = Wroot[g * 4096 + (k - 64) * 64 + h2];
        else              w = Wg   [g * 4096 + (k - 128) * 64 + h2];
        float hi, lo;
        tf32split(w, hi, lo);
        g_Wc_hi[idx] = hi;
        g_Wc_lo[idx] = lo;
    }
    if (idx < G4H) g_bc[idx] = brel[idx] + bg[idx];
}

// ---------------- per-timestep kernels ----------------
// column stats with last-block finalize (zero + stats + finalize fused)
__global__ void k_colstats(const float* __restrict__ xt) {
    __shared__ float ss[256], sq[256];
    __shared__ int islast;
    int f = threadIdx.x & 63, slot = threadIdx.x >> 6;
    float s = 0.f, q = 0.f;
    for (int n = blockIdx.x * 4 + slot; n < NN; n += gridDim.x * 4) {
        float v = xt[n * 64 + f];
        s += v; q += v * v;
    }
    ss[threadIdx.x] = s; sq[threadIdx.x] = q;
    __syncthreads();
    if (slot == 0) {
        s = ss[f] + ss[f + 64] + ss[f + 128] + ss[f + 192];
        q = sq[f] + sq[f + 64] + sq[f + 128] + sq[f + 192];
        atomicAdd(&g_colsum[f], s);
        atomicAdd(&g_colsq[f], q);
    }
    __syncthreads();
    if (threadIdx.x == 0) {
        __threadfence();
        islast = (atomicAdd(&g_cs_ticket, 1u) == gridDim.x - 1);
    }
    __syncthreads();
    if (islast && threadIdx.x < 64) {
        float fs = atomicAdd(&g_colsum[threadIdx.x], 0.f);
        float fq = atomicAdd(&g_colsq[threadIdx.x], 0.f);
        float mean = fs * (1.f / NN);
        float var = (fq - fs * fs * (1.f / NN)) * (1.f / (NN - 1));
        float sd = sqrtf(fmaxf(var, 0.f));
        g_mean[threadIdx.x] = mean;
        g_rinv[threadIdx.x] = 1.f / (sd + 1e-6f);
        g_colsum[threadIdx.x] = 0.f;
        g_colsq[threadIdx.x] = 0.f;
        if (threadIdx.x == 0) g_cs_ticket = 0u;
    }
}

__global__ void k_prep(const float* __restrict__ xt) {
    int i = blockIdx.x * blockDim.x + threadIdx.x;
    if (i >= NN * FF) return;
    int n = i >> 6, f = i & 63;
    float xn = (xt[i] - g_mean[f]) * g_rinv[f];
    float* Ar = g_A + (long)n * KA;
    Ar[f] = 0.f;                       // agg_x accumulator
    Ar[64 + f] = xn;                   // normalized x
    Ar[128 + f] = g_self[n] * g_h[i];  // GCN self-loop seed
}

__global__ void k_scatter(const float* __restrict__ w) {
    int gw = (blockIdx.x * blockDim.x + threadIdx.x) >> 5;
    int lane = threadIdx.x & 31;
    if (gw >= EE) return;
    int s = 0, d = 0; float ww = 0.f, gn = 0.f;
    if (lane == 0) {
        s = g_src[gw]; d = g_dst[gw];
        ww = w[gw]; gn = g_gcn[gw];
    }
    s  = __shfl_sync(0xffffffffu, s, 0);
    d  = __shfl_sync(0xffffffffu, d, 0);
    ww = __shfl_sync(0xffffffffu, ww, 0);
    gn = __shfl_sync(0xffffffffu, gn, 0);
    const float* As = g_A + (long)s * KA + 64;
    const float* hs = g_h + (long)s * 64;
    float* Ad = g_A + (long)d * KA;
    atomicAdd(Ad + lane,          ww * As[lane]);
    atomicAdd(Ad + lane + 32,     ww * As[lane + 32]);
    atomicAdd(Ad + 128 + lane,       gn * hs[lane]);
    atomicAdd(Ad + 128 + lane + 32,  gn * hs[lane + 32]);
}

// gates = A[NN,192] @ Wc[192,256] + bc, fused with LSTM-cell update.
// tf32 mma with 3-product split (~fp32 accuracy).
// Block: 64 rows x 256 cols, 8 warps (wm in {0,1}, wn in {0..3}).
// Warp n-tiles are gate-interleaved: cols {g*64 + wn*16 + s*8} for g=0..3, s=0..1,
// so each warp owns all 4 gates of its 16 columns -> in-register epilogue.
__global__ void __launch_bounds__(256) k_gemm_tc() {
    __shared__ float As_hi[64][18], As_lo[64][18];
    __shared__ float Bs_hi[BK][264], Bs_lo[BK][264];
    __shared__ float sbc[256];
    int tid = threadIdx.x;
    int lane = tid & 31, warp = tid >> 5;
    int wm = warp >> 2, wn = warp & 3;
    int gq = lane >> 2, tg = lane & 3;
    int r0 = blockIdx.x * 64;
    sbc[tid] = g_bc[tid];

    float acc[2][4][2][4];
#pragma unroll
    for (int a = 0; a < 2; a++)
#pragma unroll
        for (int b = 0; b < 4; b++)
#pragma unroll
            for (int cc = 0; cc < 2; cc++)
#pragma unroll
                for (int d = 0; d < 4; d++) acc[a][b][cc][d] = 0.f;

    int arow = tid >> 2;               // 0..63
    int ac4  = (tid & 3) * 4;          // 0,4,8,12
    bool rowok = (r0 + arow) < NN;
    const float* Abase = g_A + (long)(r0 + arow) * KA + ac4;

    for (int k0 = 0; k0 < KA; k0 += BK) {
        // ---- load A tile 64x16, split hi/lo ----
        float4 av = rowok ? *(const float4*)(Abase + k0) : make_float4(0.f, 0.f, 0.f, 0.f);
        {
            float h, l;
            tf32split(av.x, h, l); As_hi[arow][ac4 + 0] = h; As_lo[arow][ac4 + 0] = l;
            tf32split(av.y, h, l); As_hi[arow][ac4 + 1] = h; As_lo[arow][ac4 + 1] = l;
            tf32split(av.z, h, l); As_hi[arow][ac4 + 2] = h; As_lo[arow][ac4 + 2] = l;
            tf32split(av.w, h, l); As_hi[arow][ac4 + 3] = h; As_lo[arow][ac4 + 3] = l;
        }
        // ---- load B tile 16x256 (pre-split) ----
#pragma unroll
        for (int i = 0; i < 4; i++) {
            int flat = i * 256 + tid;
            int br = flat >> 6, bc4 = (flat & 63) * 4;
            float4 bh = *(const float4*)(g_Wc_hi + (long)(k0 + br) * G4H + bc4);
            float4 bl = *(const float4*)(g_Wc_lo + (long)(k0 + br) * G4H + bc4);
            Bs_hi[br][bc4 + 0] = bh.x; Bs_hi[br][bc4 + 1] = bh.y;
            Bs_hi[br][bc4 + 2] = bh.z; Bs_hi[br][bc4 + 3] = bh.w;
            Bs_lo[br][bc4 + 0] = bl.x; Bs_lo[br][bc4 + 1] = bl.y;
            Bs_lo[br][bc4 + 2] = bl.z; Bs_lo[br][bc4 + 3] = bl.w;
        }
        __syncthreads();

#pragma unroll
        for (int ks = 0; ks < 2; ks++) {
            unsigned ahi[2][4], alo[2][4];
#pragma unroll
            for (int mi = 0; mi < 2; mi++)
#pragma unroll
                for (int q = 0; q < 4; q++) {
                    int ar = wm * 32 + mi * 16 + gq + ((q & 1) << 3);
                    int acx = ks * 8 + tg + ((q >> 1) << 2);
                    ahi[mi][q] = __float_as_uint(As_hi[ar][acx]);
                    alo[mi][q] = __float_as_uint(As_lo[ar][acx]);
                }
#pragma unroll
            for (int gg = 0; gg < 4; gg++)
#pragma unroll
                for (int s = 0; s < 2; s++) {
                    int cb = gg * 64 + wn * 16 + s * 8 + gq;
                    int kr = ks * 8 + tg;
                    unsigned bh0 = __float_as_uint(Bs_hi[kr][cb]);
                    unsigned bh1 = __float_as_uint(Bs_hi[kr + 4][cb]);
                    unsigned bl0 = __float_as_uint(Bs_lo[kr][cb]);
                    unsigned bl1 = __float_as_uint(Bs_lo[kr + 4][cb]);
#pragma unroll
                    for (int mi = 0; mi < 2; mi++) {
                        float* C = acc[mi][gg][s];
                        MMA_TF32(C[0], C[1], C[2], C[3],
                                 alo[mi][0], alo[mi][1], alo[mi][2], alo[mi][3], bh0, bh1);
                        MMA_TF32(C[0], C[1], C[2], C[3],
                                 ahi[mi][0], ahi[mi][1], ahi[mi][2], ahi[mi][3], bl0, bl1);
                        MMA_TF32(C[0], C[1], C[2], C[3],
                                 ahi[mi][0], ahi[mi][1], ahi[mi][2], ahi[mi][3], bh0, bh1);
                    }
                }
        }
        __syncthreads();
    }

    // ---- fused bias + LSTM-cell epilogue ----
#pragma unroll
    for (int mi = 0; mi < 2; mi++)
#pragma unroll
        for (int s = 0; s < 2; s++) {
#pragma unroll
            for (int half = 0; half < 2; half++) {
                int row = r0 + wm * 32 + mi * 16 + gq + half * 8;
                if (row < NN) {
#pragma unroll
                    for (int cc = 0; cc < 2; cc++) {
                        int j = wn * 16 + s * 8 + tg * 2 + cc;
                        int ri = half * 2 + cc;
                        float gi = acc[mi][0][s][ri] + sbc[j];
                        float gf = acc[mi][1][s][ri] + sbc[64 + j];
                        float go = acc[mi][2][s][ri] + sbc[128 + j];
                        float gm = acc[mi][3][s][ri] + sbc[192 + j];
                        float ii = sigm(gi);
                        float ff = sigm(gf);
                        float oo = sigm(go);
                        float mm = fmaxf(gm, 0.f);
                        long idx = (long)row * 64 + j;
                        float c = tanhf(ii * mm + ff * g_c[idx]);
                        g_c[idx] = c;
                        g_h[idx] = oo * tanhf(c);
                    }
                }
            }
        }
}

// ---------------- DGPool ----------------
__global__ void k_vnorm(const float* __restrict__ pv) {
    __shared__ float red[64];
    int t = threadIdx.x;
    float v = pv[t];
    red[t] = v * v;
    __syncthreads();
    for (int s = 32; s > 0; s >>= 1) { if (t < s) red[t] += red[t + s]; __syncthreads(); }
    g_v[t] = v / (sqrtf(red[0]) + 1e-8f);
}

__global__ void k_scores() {
    __shared__ float ws[8];
    __shared__ int islast;
    int lane = threadIdx.x & 31, w = threadIdx.x >> 5;
    int n = blockIdx.x * 8 + w;
    float p = 0.f;
    if (n < NN)
        p = g_h[n * 64 + lane] * g_v[lane] + g_h[n * 64 + 32 + lane] * g_v[32 + lane];
    for (int o = 16; o; o >>= 1) p += __shfl_down_sync(0xffffffffu, p, o);
    if (lane == 0) {
        if (n < NN) g_raw[n] = p;
        ws[w] = (n < NN) ? p : 0.f;
    }
    __syncthreads();
    if (threadIdx.x == 0) {
        float s = 0.f, q = 0.f;
        for (int i = 0; i < 8; i++) { s += ws[i]; q += ws[i] * ws[i]; }
        atomicAdd(&g_ssum, s);
        atomicAdd(&g_ssq, q);
        __threadfence();
        islast = (atomicAdd(&g_sc_ticket, 1u) == gridDim.x - 1);
    }
    __syncthreads();
    if (islast && threadIdx.x == 0) {
        float fs = atomicAdd(&g_ssum, 0.f);
        float fq = atomicAdd(&g_ssq, 0.f);
        float mean = fs * (1.f / NN);
        float var = fq * (1.f / NN) - mean * mean;
        g_smean = mean;
        g_sinv = 1.f / (sqrtf(fmaxf(var, 0.f)) + 1e-8f);
        g_sc_ticket = 0u;
    }
}

__global__ void k_standardize(float* __restrict__ out) {
    int n = blockIdx.x * blockDim.x + threadIdx.x;
    float pl = 0.f;
    if (n < NN) {
        float s = (g_raw[n] - g_smean) * g_sinv;
        out[1 + n] = s;
        float sg = sigm(s);
        g_sig[n] = sg;
        unsigned u = __float_as_uint(s);
        u = (u & 0x80000000u) ? ~u : (u | 0x80000000u);
        g_key[n] = u;
        pl = sg * (1.f - sg);
    }
    for (int o = 16; o; o >>= 1) pl += __shfl_down_sync(0xffffffffu, pl, o);
    __shared__ float sred[8];
    if ((threadIdx.x & 31) == 0) sred[threadIdx.x >> 5] = pl;
    __syncthreads();
    if (threadIdx.x == 0) {
        float s = 0.f;
        for (int i = 0; i < 8; i++) s += sred[i];
        atomicAdd(&g_ploss, s);
    }
}

// one radix pass: histogram + (last block) scan, fused via ticket
__global__ void k_histscan(int shift) {
    __shared__ unsigned sh[256];
    __shared__ int islast;
    sh[threadIdx.x] = 0u;
    __syncthreads();
    unsigned pref = g_prefix;
    int n = blockIdx.x * blockDim.x + threadIdx.x;
    if (n < NN) {
        unsigned k = g_key[n];
        bool cand = (shift == 24) || ((k >> (shift + 8)) == (pref >> (shift + 8)));
        if (cand) atomicAdd(&sh[(k >> shift) & 255u], 1u);
    }
    __syncthreads();
    if (sh[threadIdx.x]) atomicAdd(&g_hist[threadIdx.x], sh[threadIdx.x]);
    __syncthreads();
    if (threadIdx.x == 0) {
        __threadfence();
        islast = (atomicAdd(&g_h_ticket, 1u) == gridDim.x - 1);
    }
    __syncthreads();
    if (islast) {
        unsigned v = atomicAdd(&g_hist[threadIdx.x], 0u);
        sh[threadIdx.x] = v;
        g_hist[threadIdx.x] = 0u;
        __syncthreads();
        if (threadIdx.x == 0) {
            unsigned kk = g_kk, cum = 0u;
            for (int b = 255; b >= 0; b--) {
                unsigned c = sh[b];
                if (cum + c >= kk) {
                    g_prefix |= ((unsigned)b) << shift;
                    g_kk = kk - cum;
                    break;
                }
                cum += c;
            }
            g_h_ticket = 0u;
        }
    }
}

__global__ void k_sumhigh() {
    __shared__ float acc[64];
    if (threadIdx.x < 64) acc[threadIdx.x] = 0.f;
    __syncthreads();
    int lane = threadIdx.x & 31, w = threadIdx.x >> 5;
    int n = blockIdx.x * 8 + w;
    if (n < NN) {
        int inc = 0;
        if (lane == 0) {
            unsigned key = g_key[n], tau = g_prefix;
            if (key > tau) inc = 1;
            else if (key == tau) {
                unsigned tk = atomicAdd(&g_ticket, 1u);
                inc = (tk < g_kk) ? 1 : 0;
            }
        }
        inc = __shfl_sync(0xffffffffu, inc, 0);
        if (inc) {
            float sg = g_sig[n];
            atomicAdd(&acc[lane],      g_h[n * 64 + lane] * sg);
            atomicAdd(&acc[lane + 32], g_h[n * 64 + lane + 32] * sg);
        }
    }
    __syncthreads();
    if (threadIdx.x < 64) atomicAdd(&g_high[threadIdx.x], acc[threadIdx.x]);
}

// ---------------- raw-fMRI LSTM ----------------
__global__ void k_Ggemm(const float* __restrict__ Wih, const float* __restrict__ ts) {
    __shared__ float sW[32][65];
    __shared__ float sT[32][51];
    int r0 = blockIdx.y * 64;
    int kbeg = blockIdx.x * 313;
    int kend = min(NN, kbeg + 313);
    int tid = threadIdx.x;
    int r = tid & 63, tq = tid >> 6;
    float acc[13];
#pragma unroll
    for (int j = 0; j < 13; j++) acc[j] = 0.f;

    for (int k0 = kbeg; k0 < kend; k0 += 32) {
#pragma unroll
        for (int i = 0; i < 8; i++) {
            int flat = i * 256 + tid;
            int kk = flat & 31, rr = flat >> 5;
            int kg = k0 + kk;
            sW[kk][rr] = (kg < kend) ? Wih[(long)(r0 + rr) * NN + kg] : 0.f;
        }
#pragma unroll
        for (int i = 0; i < 7; i++) {
            int flat = i * 256 + tid;
            if (flat < 1600) {
                int kk = flat & 31, t = flat >> 5;
                int kg = k0 + kk;
                sT[kk][t] = (kg < kend) ? ts[(long)t * NN + kg] : 0.f;
            }
        }
        __syncthreads();
#pragma unroll
        for (int kk = 0; kk < 32; kk++) {
            float wv = sW[kk][r];
#pragma unroll
            for (int j = 0; j < 13; j++) {
                int t = tq + 4 * j;
                if (t < TSN) acc[j] += wv * sT[kk][t];
            }
        }
        __syncthreads();
    }
#pragma unroll
    for (int j = 0; j < 13; j++) {
        int t = tq + 4 * j;
        if (t < TSN) atomicAdd(&g_G[t * G4H + r0 + r], acc[j]);
    }
}

__global__ void k_lstm(const float* __restrict__ Whh, const float* __restrict__ bih,
                       const float* __restrict__ bhh) {
    __shared__ float sh[64], scc[64], sg[256];
    int r = threadIdx.x;
    float wr[64];
#pragma unroll
    for (int m = 0; m < 64; m++) wr[m] = Whh[r * 64 + m];
    float bias = bih[r] + bhh[r];
    if (r < 64) { sh[r] = 0.f; scc[r] = 0.f; }
    __syncthreads();
    for (int t = 0; t < TSN; t++) {
        float a0 = 0.f, a1 = 0.f, a2 = 0.f, a3 = 0.f;
#pragma unroll
        for (int m = 0; m < 64; m += 4) {
            a0 += wr[m] * sh[m];
            a1 += wr[m + 1] * sh[m + 1];
            a2 += wr[m + 2] * sh[m + 2];
            a3 += wr[m + 3] * sh[m + 3];
        }
        sg[r] = g_G[t * G4H + r] + bias + ((a0 + a1) + (a2 + a3));
        __syncthreads();
        if (r < 64) {
            float gi = sg[r], gf = sg[64 + r], gg = sg[128 + r], go = sg[192 + r];
            float c = sigm(gf) * scc[r] + sigm(gi) * tanhf(gg);
            scc[r] = c;
            sh[r] = sigm(go) * tanhf(c);
        }
        __syncthreads();
    }
    if (r < 64) g_hl[r] = sh[r];
}

// ---------------- fusion head ----------------
__global__ void k_final(const float* __restrict__ lng, const float* __restrict__ lnb,
                        const float* __restrict__ W1, const float* __restrict__ b1,
                        const float* __restrict__ W2, const float* __restrict__ b2,
                        float* __restrict__ out) {
    __shared__ float red[128], sf[128], sz[64];
    int tid = threadIdx.x;
    float x = (tid < 64) ? g_high[tid] * (1.f / KSEL) : g_hl[tid - 64];
    red[tid] = x;
    __syncthreads();
    for (int s = 64; s > 0; s >>= 1) { if (tid < s) red[tid] += red[tid + s]; __syncthreads(); }
    float mean = red[0] * (1.f / 128.f);
    __syncthreads();
    float d = x - mean;
    red[tid] = d * d;
    __syncthreads();
    for (int s = 64; s > 0; s >>= 1) { if (tid < s) red[tid] += red[tid + s]; __syncthreads(); }
    float var = red[0] * (1.f / 128.f);
    float y = d * rsqrtf(var + 1e-5f) * lng[tid] + lnb[tid];
    __syncthreads();
    sf[tid] = y;
    __syncthreads();
    if (tid < 64) {
        float a = b1[tid];
        for (int j = 0; j < 128; j++) a += sf[j] * W1[j * 64 + tid];
        sz[tid] = fmaxf(a, 0.f);
    }
    __syncthreads();
    red[tid] = (tid < 64) ? sz[tid] * W2[tid] : 0.f;
    __syncthreads();
    for (int s = 64; s > 0; s >>= 1) { if (tid < s) red[tid] += red[tid + s]; __syncthreads(); }
    if (tid == 0) out[0] = red[0] + b2[0];
    if (tid == 1) out[NN + 1] = g_ploss * (1.f / NN);
}

// ---------------- launch ----------------
extern "C" void kernel_launch(void* const* d_in, const int* in_sizes, int n_in,
                              void* d_out, int out_size) {
    const float* xs   = (const float*)d_in[0];
    const void*  ei   = d_in[1];
    const float* ea   = (const float*)d_in[2];
    const float* h0   = (const float*)d_in[3];
    const float* c0   = (const float*)d_in[4];
    const float* ts   = (const float*)d_in[5];
    const float* Wrel = (const float*)d_in[6];
    const float* brel = (const float*)d_in[7];
    const float* Wroot= (const float*)d_in[8];
    const float* Wg   = (const float*)d_in[9];
    const float* bg   = (const float*)d_in[10];
    const float* pool = (const float*)d_in[11];
    const float* lng  = (const float*)d_in[12];
    const float* lnb  = (const float*)d_in[13];
    const float* Wih  = (const float*)d_in[14];
    const float* Whh  = (const float*)d_in[15];
    const float* bih  = (const float*)d_in[16];
    const float* bhh  = (const float*)d_in[17];
    const float* W1   = (const float*)d_in[18];
    const float* b1   = (const float*)d_in[19];
    const float* W2   = (const float*)d_in[20];
    const float* b2   = (const float*)d_in[21];
    float* out = (float*)d_out;

    k_detect<<<1, 32>>>(ei);
    k_decode_zero<<<(EE + 255) / 256, 256>>>(ei);
    k_deg<<<(EE + 255) / 256, 256>>>();
    k_init_nodes<<<(NN * HH + 255) / 256, 256>>>(h0, c0);
    k_gcn<<<(EE + 255) / 256, 256>>>();
    k_wc<<<(KA * G4H + 255) / 256, 256>>>(Wrel, brel, Wroot, Wg, bg);

    for (int t = 0; t < TT; t++) {
        const float* xt = xs + (long)t * NN * FF;
        k_colstats<<<160, 256>>>(xt);
        k_prep<<<(NN * FF + 255) / 256, 256>>>(xt);
        k_scatter<<<EE / 8, 256>>>(ea + (long)t * EE);
        k_gemm_tc<<<(NN + 63) / 64, 256>>>();
    }

    k_vnorm<<<1, 64>>>(pool);
    k_scores<<<(NN + 7) / 8, 256>>>();
    k_standardize<<<(NN + 255) / 256, 256>>>(out);
    for (int p = 0; p < 4; p++) k_histscan<<<(NN + 255) / 256, 256>>>(24 - 8 * p);
    k_sumhigh<<<(NN + 7) / 8, 256>>>();

    k_Ggemm<<<dim3(64, 4), 256>>>(Wih, ts);
    k_lstm<<<1, 256>>>(Whh, bih, bhh);
    k_final<<<1, 128>>>(lng, lnb, W1, b1, W2, b2, out);
}

// round 4
// speedup vs baseline: 1.0949x; 1.0949x over previous
#include <cuda_runtime.h>
#include <stdint.h>

#define TT   4
#define NN   20000
#define EE   320000
#define FF   64
#define HH   64
#define TSN  50
#define G4H  256      // 4 gates * H
#define KA   192      // agg_x(64) | x_norm(64) | agg_h(64)
#define KSEL 10000    // top-k
#define BK   16

// ---------------- device scratch (static, allocation-free) ----------------
__device__ __align__(16) float g_A[NN * KA];
__device__ __align__(16) float g_h[NN * HH];
__device__ __align__(16) float g_c[NN * HH];
__device__ float g_dinv[NN];
__device__ float g_self[NN];
__device__ int   g_cnt[NN];
__device__ int   g_cursor[NN];
__device__ int   g_rowptr[NN + 1];
__device__ int   g_src[EE];
__device__ int   g_dst[EE];
__device__ int   g_s_src[EE];
__device__ int   g_s_eid[EE];
__device__ float g_s_gcn[EE];
__device__ int   g_is64;
__device__ __align__(16) float g_Wc_hi[KA * G4H];
__device__ __align__(16) float g_Wc_lo[KA * G4H];
__device__ __align__(16) float g_bc[G4H];
__device__ float g_colsum[FF];
__device__ float g_colsq[FF];
__device__ float g_mean[FF];
__device__ float g_rinv[FF];
__device__ float g_v[HH];
__device__ float g_raw[NN];
__device__ float g_sig[NN];
__device__ unsigned g_key[NN];
__device__ float g_high[HH];
__device__ __align__(16) float g_G[TSN * G4H];
__device__ float g_hl[HH];
__device__ unsigned g_hist[256];
__device__ unsigned g_prefix;
__device__ unsigned g_kk;
__device__ unsigned g_ticket;
__device__ unsigned g_cs_ticket, g_h_ticket, g_sc_ticket;
__device__ float g_ssum, g_ssq, g_smean, g_sinv, g_ploss;

__device__ __forceinline__ float sigm(float x) { return 1.f / (1.f + expf(-x)); }

__device__ __forceinline__ unsigned f2tf32(float x) {
    unsigned r;
    asm("cvt.rna.tf32.f32 %0, %1;" : "=r"(r) : "f"(x));
    return r;
}

__device__ __forceinline__ void tf32split(float x, float& hi, float& lo) {
    unsigned hb = f2tf32(x);
    float h = __uint_as_float(hb);
    float l = x - h;
    hi = h;
    lo = __uint_as_float(f2tf32(l));
}

#define MMA_TF32(c0, c1, c2, c3, a0, a1, a2, a3, b0, b1)                         \
    asm volatile("mma.sync.aligned.m16n8k8.row.col.f32.tf32.tf32.f32 "           \
                 "{%0,%1,%2,%3}, {%4,%5,%6,%7}, {%8,%9}, {%0,%1,%2,%3};"         \
                 : "+f"(c0), "+f"(c1), "+f"(c2), "+f"(c3)                        \
                 : "r"(a0), "r"(a1), "r"(a2), "r"(a3), "r"(b0), "r"(b1))

// ---------------- preamble: detect dtype, zero, decode+count ----------------
__global__ void k_detect_zero(const void* eiraw) {
    int i = blockIdx.x * blockDim.x + threadIdx.x;
    if (i < NN) { g_cnt[i] = 0; g_cursor[i] = 0; }
    if (i < TSN * G4H) g_G[i] = 0.f;
    if (i < HH) g_high[i] = 0.f;
    if (i < 256) g_hist[i] = 0u;
    if (i < FF) { g_colsum[i] = 0.f; g_colsq[i] = 0.f; }
    if (i == 0) {
        const long long* p = (const long long*)eiraw;
        int ok = 1;
        for (int j = 0; j < 8; j++) {
            long long v = p[j];
            if (v < 0 || v >= NN) ok = 0;
        }
        g_is64 = ok;
        g_prefix = 0u; g_kk = KSEL; g_ticket = 0u;
        g_cs_ticket = 0u; g_h_ticket = 0u; g_sc_ticket = 0u;
        g_ssum = 0.f; g_ssq = 0.f; g_ploss = 0.f;
    }
}

__global__ void k_decode_count(const void* eiraw) {
    int e = blockIdx.x * blockDim.x + threadIdx.x;
    if (e >= EE) return;
    int s, d;
    if (g_is64) {
        const long long* p = (const long long*)eiraw;
        s = (int)p[e];
        d = (int)p[EE + e];
    } else {
        const int* p = (const int*)eiraw;
        s = p[e];
        d = p[EE + e];
    }
    s = min(max(s, 0), NN - 1);
    d = min(max(d, 0), NN - 1);
    g_src[e] = s;
    g_dst[e] = d;
    atomicAdd(&g_cnt[d], 1);
}

__global__ void k_init_nodes(const float* __restrict__ h0, const float* __restrict__ c0) {
    int i = blockIdx.x * blockDim.x + threadIdx.x;
    if (i < NN) {
        float d = (float)g_cnt[i] + 1.f;
        g_dinv[i] = rsqrtf(d);
        g_self[i] = 1.f / d;
    }
    if (i < NN * HH) { g_h[i] = h0[i]; g_c[i] = c0[i]; }
}

// exclusive prefix over g_cnt -> g_rowptr (single block, 1024 threads)
__global__ void k_prefix() {
    __shared__ int sh[1024];
    __shared__ int carry;
    int t = threadIdx.x;
    if (t == 0) carry = 0;
    __syncthreads();
    for (int c = 0; c < (NN + 1023) / 1024; c++) {
        int i = c * 1024 + t;
        int v = (i < NN) ? g_cnt[i] : 0;
        sh[t] = v;
        __syncthreads();
        for (int o = 1; o < 1024; o <<= 1) {
            int u = (t >= o) ? sh[t - o] : 0;
            __syncthreads();
            sh[t] += u;
            __syncthreads();
        }
        int incl = sh[t];
        int base = carry;
        if (i < NN) g_rowptr[i] = base + incl - v;
        __syncthreads();
        if (t == 1023) carry = base + incl;
        __syncthreads();
    }
    if (t == 0) g_rowptr[NN] = carry;
}

__global__ void k_sortedges() {
    int e = blockIdx.x * blockDim.x + threadIdx.x;
    if (e >= EE) return;
    int s = g_src[e], d = g_dst[e];
    int pos = g_rowptr[d] + atomicAdd(&g_cursor[d], 1);
    g_s_src[pos] = s;
    g_s_eid[pos] = e;
    g_s_gcn[pos] = g_dinv[s] * g_dinv[d];
}

__global__ void k_wc(const float* __restrict__ Wrel, const float* __restrict__ brel,
                     const float* __restrict__ Wroot, const float* __restrict__ Wg,
                     const float* __restrict__ bg) {
    int idx = blockIdx.x * blockDim.x + threadIdx.x;
    if (idx < KA * G4H) {
        int k = idx / G4H, col = idx % G4H;
        int g = col >> 6, h2 = col & 63;
        float w;
        if (k < 64)       w = Wrel [g * 4096 + k * 64 + h2];
        else if (k < 128) w = Wroot[g * 4096 + (k - 64) * 64 + h2];
        else              w = Wg   [g * 4096 + (k - 128) * 64 + h2];
        float hi, lo;
        tf32split(w, hi, lo);
        g_Wc_hi[idx] = hi;
        g_Wc_lo[idx] = lo;
    }
    if (idx < G4H) g_bc[idx] = brel[idx] + bg[idx];
}

// ---------------- per-timestep kernels ----------------
__global__ void k_colstats(const float* __restrict__ xt) {
    __shared__ float ss[256], sq[256];
    __shared__ int islast;
    int f = threadIdx.x & 63, slot = threadIdx.x >> 6;
    float s = 0.f, q = 0.f;
    for (int n = blockIdx.x * 4 + slot; n < NN; n += gridDim.x * 4) {
        float v = xt[n * 64 + f];
        s += v; q += v * v;
    }
    ss[threadIdx.x] = s; sq[threadIdx.x] = q;
    __syncthreads();
    if (slot == 0) {
        s = ss[f] + ss[f + 64] + ss[f + 128] + ss[f + 192];
        q = sq[f] + sq[f + 64] + sq[f + 128] + sq[f + 192];
        atomicAdd(&g_colsum[f], s);
        atomicAdd(&g_colsq[f], q);
    }
    __syncthreads();
    if (threadIdx.x == 0) {
        __threadfence();
        islast = (atomicAdd(&g_cs_ticket, 1u) == gridDim.x - 1);
    }
    __syncthreads();
    if (islast && threadIdx.x < 64) {
        float fs = atomicAdd(&g_colsum[threadIdx.x], 0.f);
        float fq = atomicAdd(&g_colsq[threadIdx.x], 0.f);
        float mean = fs * (1.f / NN);
        float var = (fq - fs * fs * (1.f / NN)) * (1.f / (NN - 1));
        float sd = sqrtf(fmaxf(var, 0.f));
        g_mean[threadIdx.x] = mean;
        g_rinv[threadIdx.x] = 1.f / (sd + 1e-6f);
        g_colsum[threadIdx.x] = 0.f;
        g_colsq[threadIdx.x] = 0.f;
        if (threadIdx.x == 0) g_cs_ticket = 0u;
    }
}

__global__ void k_prep(const float* __restrict__ xt) {
    int i = blockIdx.x * blockDim.x + threadIdx.x;
    if (i >= NN * FF) return;
    int n = i >> 6, f = i & 63;
    float xn = (xt[i] - g_mean[f]) * g_rinv[f];
    float* Ar = g_A + (long)n * KA;
    Ar[64 + f] = xn;                   // normalized x
    Ar[128 + f] = g_self[n] * g_h[i];  // GCN self-loop seed
}

// one warp per destination node; sequential, non-atomic aggregation
__global__ void k_gather(const float* __restrict__ w) {
    int node = (blockIdx.x * blockDim.x + threadIdx.x) >> 5;
    int lane = threadIdx.x & 31;
    if (node >= NN) return;
    int beg = g_rowptr[node], end = g_rowptr[node + 1];
    float ax0 = 0.f, ax1 = 0.f, ah0 = 0.f, ah1 = 0.f;
    for (int e = beg; e < end; e++) {
        int s = g_s_src[e];
        float wv = w[g_s_eid[e]];
        float gn = g_s_gcn[e];
        const float2* xr = (const float2*)(g_A + (long)s * KA + 64);
        const float2* hr = (const float2*)(g_h + (long)s * 64);
        float2 xv = xr[lane];
        float2 hv = hr[lane];
        ax0 += wv * xv.x; ax1 += wv * xv.y;
        ah0 += gn * hv.x; ah1 += gn * hv.y;
    }
    float2* axp = (float2*)(g_A + (long)node * KA);
    axp[lane] = make_float2(ax0, ax1);
    float2* ahp = (float2*)(g_A + (long)node * KA + 128);
    float2 seed = ahp[lane];
    seed.x += ah0; seed.y += ah1;
    ahp[lane] = seed;
}

// gates = A[NN,192] @ Wc[192,256] + bc, fused LSTM-cell update (3xTF32 mma)
__global__ void __launch_bounds__(256) k_gemm_tc() {
    __shared__ float As_hi[64][18], As_lo[64][18];
    __shared__ float Bs_hi[BK][264], Bs_lo[BK][264];
    __shared__ float sbc[256];
    int tid = threadIdx.x;
    int lane = tid & 31, warp = tid >> 5;
    int wm = warp >> 2, wn = warp & 3;
    int gq = lane >> 2, tg = lane & 3;
    int r0 = blockIdx.x * 64;
    sbc[tid] = g_bc[tid];

    float acc[2][4][2][4];
#pragma unroll
    for (int a = 0; a < 2; a++)
#pragma unroll
        for (int b = 0; b < 4; b++)
#pragma unroll
            for (int cc = 0; cc < 2; cc++)
#pragma unroll
                for (int d = 0; d < 4; d++) acc[a][b][cc][d] = 0.f;

    int arow = tid >> 2;
    int ac4  = (tid & 3) * 4;
    bool rowok = (r0 + arow) < NN;
    const float* Abase = g_A + (long)(r0 + arow) * KA + ac4;

    for (int k0 = 0; k0 < KA; k0 += BK) {
        float4 av = rowok ? *(const float4*)(Abase + k0) : make_float4(0.f, 0.f, 0.f, 0.f);
        {
            float h, l;
            tf32split(av.x, h, l); As_hi[arow][ac4 + 0] = h; As_lo[arow][ac4 + 0] = l;
            tf32split(av.y, h, l); As_hi[arow][ac4 + 1] = h; As_lo[arow][ac4 + 1] = l;
            tf32split(av.z, h, l); As_hi[arow][ac4 + 2] = h; As_lo[arow][ac4 + 2] = l;
            tf32split(av.w, h, l); As_hi[arow][ac4 + 3] = h; As_lo[arow][ac4 + 3] = l;
        }
#pragma unroll
        for (int i = 0; i < 4; i++) {
            int flat = i * 256 + tid;
            int br = flat >> 6, bc4 = (flat & 63) * 4;
            float4 bh = *(const float4*)(g_Wc_hi + (long)(k0 + br) * G4H + bc4);
            float4 bl = *(const float4*)(g_Wc_lo + (long)(k0 + br) * G4H + bc4);
            Bs_hi[br][bc4 + 0] = bh.x; Bs_hi[br][bc4 + 1] = bh.y;
            Bs_hi[br][bc4 + 2] = bh.z; Bs_hi[br][bc4 + 3] = bh.w;
            Bs_lo[br][bc4 + 0] = bl.x; Bs_lo[br][bc4 + 1] = bl.y;
            Bs_lo[br][bc4 + 2] = bl.z; Bs_lo[br][bc4 + 3] = bl.w;
        }
        __syncthreads();

#pragma unroll
        for (int ks = 0; ks < 2; ks++) {
            unsigned ahi[2][4], alo[2][4];
#pragma unroll
            for (int mi = 0; mi < 2; mi++)
#pragma unroll
                for (int q = 0; q < 4; q++) {
                    int ar = wm * 32 + mi * 16 + gq + ((q & 1) << 3);
                    int acx = ks * 8 + tg + ((q >> 1) << 2);
                    ahi[mi][q] = __float_as_uint(As_hi[ar][acx]);
                    alo[mi][q] = __float_as_uint(As_lo[ar][acx]);
                }
#pragma unroll
            for (int gg = 0; gg < 4; gg++)
#pragma unroll
                for (int s = 0; s < 2; s++) {
                    int cb = gg * 64 + wn * 16 + s * 8 + gq;
                    int kr = ks * 8 + tg;
                    unsigned bh0 = __float_as_uint(Bs_hi[kr][cb]);
                    unsigned bh1 = __float_as_uint(Bs_hi[kr + 4][cb]);
                    unsigned bl0 = __float_as_uint(Bs_lo[kr][cb]);
                    unsigned bl1 = __float_as_uint(Bs_lo[kr + 4][cb]);
#pragma unroll
                    for (int mi = 0; mi < 2; mi++) {
                        float* C = acc[mi][gg][s];
                        MMA_TF32(C[0], C[1], C[2], C[3],
                                 alo[mi][0], alo[mi][1], alo[mi][2], alo[mi][3], bh0, bh1);
                        MMA_TF32(C[0], C[1], C[2], C[3],
                                 ahi[mi][0], ahi[mi][1], ahi[mi][2], ahi[mi][3], bl0, bl1);
                        MMA_TF32(C[0], C[1], C[2], C[3],
                                 ahi[mi][0], ahi[mi][1], ahi[mi][2], ahi[mi][3], bh0, bh1);
                    }
                }
        }
        __syncthreads();
    }

#pragma unroll
    for (int mi = 0; mi < 2; mi++)
#pragma unroll
        for (int s = 0; s < 2; s++) {
#pragma unroll
            for (int half = 0; half < 2; half++) {
                int row = r0 + wm * 32 + mi * 16 + gq + half * 8;
                if (row < NN) {
#pragma unroll
                    for (int cc = 0; cc < 2; cc++) {
                        int j = wn * 16 + s * 8 + tg * 2 + cc;
                        int ri = half * 2 + cc;
                        float gi = acc[mi][0][s][ri] + sbc[j];
                        float gf = acc[mi][1][s][ri] + sbc[64 + j];
                        float go = acc[mi][2][s][ri] + sbc[128 + j];
                        float gm = acc[mi][3][s][ri] + sbc[192 + j];
                        float ii = sigm(gi);
                        float ff = sigm(gf);
                        float oo = sigm(go);
                        float mm = fmaxf(gm, 0.f);
                        long idx = (long)row * 64 + j;
                        float c = tanhf(ii * mm + ff * g_c[idx]);
                        g_c[idx] = c;
                        g_h[idx] = oo * tanhf(c);
                    }
                }
            }
        }
}

// ---------------- DGPool ----------------
__global__ void k_vnorm(const float* __restrict__ pv) {
    __shared__ float red[64];
    int t = threadIdx.x;
    float v = pv[t];
    red[t] = v * v;
    __syncthreads();
    for (int s = 32; s > 0; s >>= 1) { if (t < s) red[t] += red[t + s]; __syncthreads(); }
    g_v[t] = v / (sqrtf(red[0]) + 1e-8f);
}

__global__ void k_scores() {
    __shared__ float ws[8];
    __shared__ int islast;
    int lane = threadIdx.x & 31, w = threadIdx.x >> 5;
    int n = blockIdx.x * 8 + w;
    float p = 0.f;
    if (n < NN)
        p = g_h[n * 64 + lane] * g_v[lane] + g_h[n * 64 + 32 + lane] * g_v[32 + lane];
    for (int o = 16; o; o >>= 1) p += __shfl_down_sync(0xffffffffu, p, o);
    if (lane == 0) {
        if (n < NN) g_raw[n] = p;
        ws[w] = (n < NN) ? p : 0.f;
    }
    __syncthreads();
    if (threadIdx.x == 0) {
        float s = 0.f, q = 0.f;
        for (int i = 0; i < 8; i++) { s += ws[i]; q += ws[i] * ws[i]; }
        atomicAdd(&g_ssum, s);
        atomicAdd(&g_ssq, q);
        __threadfence();
        islast = (atomicAdd(&g_sc_ticket, 1u) == gridDim.x - 1);
    }
    __syncthreads();
    if (islast && threadIdx.x == 0) {
        float fs = atomicAdd(&g_ssum, 0.f);
        float fq = atomicAdd(&g_ssq, 0.f);
        float mean = fs * (1.f / NN);
        float var = fq * (1.f / NN) - mean * mean;
        g_smean = mean;
        g_sinv = 1.f / (sqrtf(fmaxf(var, 0.f)) + 1e-8f);
        g_sc_ticket = 0u;
    }
}

__global__ void k_standardize(float* __restrict__ out) {
    int n = blockIdx.x * blockDim.x + threadIdx.x;
    float pl = 0.f;
    if (n < NN) {
        float s = (g_raw[n] - g_smean) * g_sinv;
        out[1 + n] = s;
        float sg = sigm(s);
        g_sig[n] = sg;
        unsigned u = __float_as_uint(s);
        u = (u & 0x80000000u) ? ~u : (u | 0x80000000u);
        g_key[n] = u;
        pl = sg * (1.f - sg);
    }
    for (int o = 16; o; o >>= 1) pl += __shfl_down_sync(0xffffffffu, pl, o);
    __shared__ float sred[8];
    if ((threadIdx.x & 31) == 0) sred[threadIdx.x >> 5] = pl;
    __syncthreads();
    if (threadIdx.x == 0) {
        float s = 0.f;
        for (int i = 0; i < 8; i++) s += sred[i];
        atomicAdd(&g_ploss, s);
    }
}

__global__ void k_histscan(int shift) {
    __shared__ unsigned sh[256];
    __shared__ int islast;
    sh[threadIdx.x] = 0u;
    __syncthreads();
    unsigned pref = g_prefix;
    int n = blockIdx.x * blockDim.x + threadIdx.x;
    if (n < NN) {
        unsigned k = g_key[n];
        bool cand = (shift == 24) || ((k >> (shift + 8)) == (pref >> (shift + 8)));
        if (cand) atomicAdd(&sh[(k >> shift) & 255u], 1u);
    }
    __syncthreads();
    if (sh[threadIdx.x]) atomicAdd(&g_hist[threadIdx.x], sh[threadIdx.x]);
    __syncthreads();
    if (threadIdx.x == 0) {
        __threadfence();
        islast = (atomicAdd(&g_h_ticket, 1u) == gridDim.x - 1);
    }
    __syncthreads();
    if (islast) {
        unsigned v = atomicAdd(&g_hist[threadIdx.x], 0u);
        sh[threadIdx.x] = v;
        g_hist[threadIdx.x] = 0u;
        __syncthreads();
        if (threadIdx.x == 0) {
            unsigned kk = g_kk, cum = 0u;
            for (int b = 255; b >= 0; b--) {
                unsigned c = sh[b];
                if (cum + c >= kk) {
                    g_prefix |= ((unsigned)b) << shift;
                    g_kk = kk - cum;
                    break;
                }
                cum += c;
            }
            g_h_ticket = 0u;
        }
    }
}

__global__ void k_sumhigh() {
    __shared__ float acc[64];
    if (threadIdx.x < 64) acc[threadIdx.x] = 0.f;
    __syncthreads();
    int lane = threadIdx.x & 31, w = threadIdx.x >> 5;
    int n = blockIdx.x * 8 + w;
    if (n < NN) {
        int inc = 0;
        if (lane == 0) {
            unsigned key = g_key[n], tau = g_prefix;
            if (key > tau) inc = 1;
            else if (key == tau) {
                unsigned tk = atomicAdd(&g_ticket, 1u);
                inc = (tk < g_kk) ? 1 : 0;
            }
        }
        inc = __shfl_sync(0xffffffffu, inc, 0);
        if (inc) {
            float sg = g_sig[n];
            atomicAdd(&acc[lane],      g_h[n * 64 + lane] * sg);
            atomicAdd(&acc[lane + 32], g_h[n * 64 + lane + 32] * sg);
        }
    }
    __syncthreads();
    if (threadIdx.x < 64) atomicAdd(&g_high[threadIdx.x], acc[threadIdx.x]);
}

// ---------------- raw-fMRI LSTM ----------------
__global__ void k_Ggemm(const float* __restrict__ Wih, const float* __restrict__ ts) {
    __shared__ float sW[32][65];
    __shared__ float sT[32][51];
    int r0 = blockIdx.y * 64;
    int kbeg = blockIdx.x * 313;
    int kend = min(NN, kbeg + 313);
    int tid = threadIdx.x;
    int r = tid & 63, tq = tid >> 6;
    float acc[13];
#pragma unroll
    for (int j = 0; j < 13; j++) acc[j] = 0.f;

    for (int k0 = kbeg; k0 < kend; k0 += 32) {
#pragma unroll
        for (int i = 0; i < 8; i++) {
            int flat = i * 256 + tid;
            int kk = flat & 31, rr = flat >> 5;
            int kg = k0 + kk;
            sW[kk][rr] = (kg < kend) ? Wih[(long)(r0 + rr) * NN + kg] : 0.f;
        }
#pragma unroll
        for (int i = 0; i < 7; i++) {
            int flat = i * 256 + tid;
            if (flat < 1600) {
                int kk = flat & 31, t = flat >> 5;
                int kg = k0 + kk;
                sT[kk][t] = (kg < kend) ? ts[(long)t * NN + kg] : 0.f;
            }
        }
        __syncthreads();
#pragma unroll
        for (int kk = 0; kk < 32; kk++) {
            float wv = sW[kk][r];
#pragma unroll
            for (int j = 0; j < 13; j++) {
                int t = tq + 4 * j;
                if (t < TSN) acc[j] += wv * sT[kk][t];
            }
        }
        __syncthreads();
    }
#pragma unroll
    for (int j = 0; j < 13; j++) {
        int t = tq + 4 * j;
        if (t < TSN) atomicAdd(&g_G[t * G4H + r0 + r], acc[j]);
    }
}

__global__ void k_lstm(const float* __restrict__ Whh, const float* __restrict__ bih,
                       const float* __restrict__ bhh) {
    __shared__ float sh[64], scc[64], sg[256];
    int r = threadIdx.x;
    float wr[64];
#pragma unroll
    for (int m = 0; m < 64; m++) wr[m] = Whh[r * 64 + m];
    float bias = bih[r] + bhh[r];
    if (r < 64) { sh[r] = 0.f; scc[r] = 0.f; }
    __syncthreads();
    for (int t = 0; t < TSN; t++) {
        float a0 = 0.f, a1 = 0.f, a2 = 0.f, a3 = 0.f;
#pragma unroll
        for (int m = 0; m < 64; m += 4) {
            a0 += wr[m] * sh[m];
            a1 += wr[m + 1] * sh[m + 1];
            a2 += wr[m + 2] * sh[m + 2];
            a3 += wr[m + 3] * sh[m + 3];
        }
        sg[r] = g_G[t * G4H + r] + bias + ((a0 + a1) + (a2 + a3));
        __syncthreads();
        if (r < 64) {
            float gi = sg[r], gf = sg[64 + r], gg = sg[128 + r], go = sg[192 + r];
            float c = sigm(gf) * scc[r] + sigm(gi) * tanhf(gg);
            scc[r] = c;
            sh[r] = sigm(go) * tanhf(c);
        }
        __syncthreads();
    }
    if (r < 64) g_hl[r] = sh[r];
}

// ---------------- fusion head ----------------
__global__ void k_final(const float* __restrict__ lng, const float* __restrict__ lnb,
                        const float* __restrict__ W1, const float* __restrict__ b1,
                        const float* __restrict__ W2, const float* __restrict__ b2,
                        float* __restrict__ out) {
    __shared__ float red[128], sf[128], sz[64];
    int tid = threadIdx.x;
    float x = (tid < 64) ? g_high[tid] * (1.f / KSEL) : g_hl[tid - 64];
    red[tid] = x;
    __syncthreads();
    for (int s = 64; s > 0; s >>= 1) { if (tid < s) red[tid] += red[tid + s]; __syncthreads(); }
    float mean = red[0] * (1.f / 128.f);
    __syncthreads();
    float d = x - mean;
    red[tid] = d * d;
    __syncthreads();
    for (int s = 64; s > 0; s >>= 1) { if (tid < s) red[tid] += red[tid + s]; __syncthreads(); }
    float var = red[0] * (1.f / 128.f);
    float y = d * rsqrtf(var + 1e-5f) * lng[tid] + lnb[tid];
    __syncthreads();
    sf[tid] = y;
    __syncthreads();
    if (tid < 64) {
        float a = b1[tid];
        for (int j = 0; j < 128; j++) a += sf[j] * W1[j * 64 + tid];
        sz[tid] = fmaxf(a, 0.f);
    }
    __syncthreads();
    red[tid] = (tid < 64) ? sz[tid] * W2[tid] : 0.f;
    __syncthreads();
    for (int s = 64; s > 0; s >>= 1) { if (tid < s) red[tid] += red[tid + s]; __syncthreads(); }
    if (tid == 0) out[0] = red[0] + b2[0];
    if (tid == 1) out[NN + 1] = g_ploss * (1.f / NN);
}

// ---------------- launch ----------------
extern "C" void kernel_launch(void* const* d_in, const int* in_sizes, int n_in,
                              void* d_out, int out_size) {
    const float* xs   = (const float*)d_in[0];
    const void*  ei   = d_in[1];
    const float* ea   = (const float*)d_in[2];
    const float* h0   = (const float*)d_in[3];
    const float* c0   = (const float*)d_in[4];
    const float* ts   = (const float*)d_in[5];
    const float* Wrel = (const float*)d_in[6];
    const float* brel = (const float*)d_in[7];
    const float* Wroot= (const float*)d_in[8];
    const float* Wg   = (const float*)d_in[9];
    const float* bg   = (const float*)d_in[10];
    const float* pool = (const float*)d_in[11];
    const float* lng  = (const float*)d_in[12];
    const float* lnb  = (const float*)d_in[13];
    const float* Wih  = (const float*)d_in[14];
    const float* Whh  = (const float*)d_in[15];
    const float* bih  = (const float*)d_in[16];
    const float* bhh  = (const float*)d_in[17];
    const float* W1   = (const float*)d_in[18];
    const float* b1   = (const float*)d_in[19];
    const float* W2   = (const float*)d_in[20];
    const float* b2   = (const float*)d_in[21];
    float* out = (float*)d_out;

    k_detect_zero<<<(NN + 255) / 256, 256>>>(ei);
    k_decode_count<<<(EE + 255) / 256, 256>>>(ei);
    k_init_nodes<<<(NN * HH + 255) / 256, 256>>>(h0, c0);
    k_prefix<<<1, 1024>>>();
    k_sortedges<<<(EE + 255) / 256, 256>>>();
    k_wc<<<(KA * G4H + 255) / 256, 256>>>(Wrel, brel, Wroot, Wg, bg);

    for (int t = 0; t < TT; t++) {
        const float* xt = xs + (long)t * NN * FF;
        k_colstats<<<160, 256>>>(xt);
        k_prep<<<(NN * FF + 255) / 256, 256>>>(xt);
        k_gather<<<(NN * 32 + 255) / 256, 256>>>(ea + (long)t * EE);
        k_gemm_tc<<<(NN + 63) / 64, 256>>>();
    }

    k_vnorm<<<1, 64>>>(pool);
    k_scores<<<(NN + 7) / 8, 256>>>();
    k_standardize<<<(NN + 255) / 256, 256>>>(out);
    for (int p = 0; p < 4; p++) k_histscan<<<(NN + 255) / 256, 256>>>(24 - 8 * p);
    k_sumhigh<<<(NN + 7) / 8, 256>>>();

    k_Ggemm<<<dim3(64, 4), 256>>>(Wih, ts);
    k_lstm<<<1, 256>>>(Whh, bih, bhh);
    k_final<<<1, 128>>>(lng, lnb, W1, b1, W2, b2, out);
}

// round 5
// speedup vs baseline: 1.1237x; 1.0263x over previous
#include <cuda_runtime.h>
#include <stdint.h>

#define TT   4
#define NN   20000
#define EE   320000
#define FF   64
#define HH   64
#define TSN  50
#define G4H  256
#define KX   128     // aggx(64) | xn(64)
#define KH   64      // aggh
#define KSEL 10000
#define BK   16

// ---------------- device scratch (zero-initialized at load) ----------------
__device__ __align__(16) float g_X[(long)TT * NN * KX];   // 41 MB
__device__ __align__(16) float g_P[(long)TT * NN * G4H];  // 82 MB
__device__ __align__(16) float g_AH[NN * KH];
__device__ __align__(16) float g_h[NN * HH];
__device__ __align__(16) float g_c[NN * HH];
__device__ float g_dinv[NN];
__device__ float g_self[NN];
__device__ int   g_cnt[NN];
__device__ int   g_cursor[NN];
__device__ int   g_rowptr[NN + 1];
__device__ int   g_src[EE];
__device__ int   g_dst[EE];
__device__ int   g_s_src[EE];
__device__ int   g_s_eid[EE];
__device__ float g_s_gcn[EE];
__device__ __align__(16) float g_Wx_hi[KX * G4H];
__device__ __align__(16) float g_Wx_lo[KX * G4H];
__device__ __align__(16) float g_Wg_hi[KH * G4H];
__device__ __align__(16) float g_Wg_lo[KH * G4H];
__device__ __align__(16) float g_bc[G4H];
__device__ float g_colsum[TT * FF];
__device__ float g_colsq[TT * FF];
__device__ float g_mean[TT * FF];
__device__ float g_rinv[TT * FF];
__device__ float g_v[HH];
__device__ float g_raw[NN];
__device__ float g_sig[NN];
__device__ unsigned g_key[NN];
__device__ float g_high[HH];
__device__ __align__(16) float g_G[TSN * G4H];
__device__ float g_hl[HH];
__device__ unsigned g_hist[256];
__device__ unsigned g_prefix;
__device__ unsigned g_kkleft;
__device__ unsigned g_ticket;
__device__ unsigned g_cs_ticket[TT];
__device__ unsigned g_h_ticket, g_sc_ticket;
__device__ float g_ssum, g_ssq, g_smean, g_sinv, g_ploss;

__device__ __forceinline__ float sigm(float x) { return 1.f / (1.f + expf(-x)); }

__device__ __forceinline__ unsigned f2tf32(float x) {
    unsigned r;
    asm("cvt.rna.tf32.f32 %0, %1;" : "=r"(r) : "f"(x));
    return r;
}
__device__ __forceinline__ void tf32split(float x, float& hi, float& lo) {
    float h = __uint_as_float(f2tf32(x));
    hi = h;
    lo = __uint_as_float(f2tf32(x - h));
}

#define MMA_TF32(c0, c1, c2, c3, a0, a1, a2, a3, b0, b1)                         \
    asm volatile("mma.sync.aligned.m16n8k8.row.col.f32.tf32.tf32.f32 "           \
                 "{%0,%1,%2,%3}, {%4,%5,%6,%7}, {%8,%9}, {%0,%1,%2,%3};"         \
                 : "+f"(c0), "+f"(c1), "+f"(c2), "+f"(c3)                        \
                 : "r"(a0), "r"(a1), "r"(a2), "r"(a3), "r"(b0), "r"(b1))

// ---------------- 0: decode edges (+count) + copy h0/c0 ----------------
__global__ void k_decode(const void* eiraw, const float* __restrict__ h0,
                         const float* __restrict__ c0) {
    int gid = blockIdx.x * blockDim.x + threadIdx.x;   // exactly EE threads
    const long long* p64 = (const long long*)eiraw;
    bool is64 = true;
#pragma unroll
    for (int j = 0; j < 8; j++) {
        long long v = p64[j];
        if (v < 0 || v >= NN) is64 = false;
    }
    int s, d;
    if (is64) { s = (int)p64[gid]; d = (int)p64[EE + gid]; }
    else { const int* p32 = (const int*)eiraw; s = p32[gid]; d = p32[EE + gid]; }
    s = min(max(s, 0), NN - 1);
    d = min(max(d, 0), NN - 1);
    g_src[gid] = s;
    g_dst[gid] = d;
    atomicAdd(&g_cnt[d], 1);
    for (int j = gid; j < NN * HH; j += EE) { g_h[j] = h0[j]; g_c[j] = c0[j]; }
}

// ---------------- 1: per-timestep column stats (all T at once) ----------------
__global__ void k_colstats(const float* __restrict__ xs) {
    __shared__ float ss[256], sq[256];
    __shared__ int islast;
    int t = blockIdx.y;
    const float* xt = xs + (long)t * NN * FF;
    int f = threadIdx.x & 63, slot = threadIdx.x >> 6;
    float s = 0.f, q = 0.f;
    for (int n = blockIdx.x * 4 + slot; n < NN; n += gridDim.x * 4) {
        float v = xt[n * 64 + f];
        s += v; q += v * v;
    }
    ss[threadIdx.x] = s; sq[threadIdx.x] = q;
    __syncthreads();
    if (slot == 0) {
        s = ss[f] + ss[f + 64] + ss[f + 128] + ss[f + 192];
        q = sq[f] + sq[f + 64] + sq[f + 128] + sq[f + 192];
        atomicAdd(&g_colsum[t * 64 + f], s);
        atomicAdd(&g_colsq[t * 64 + f], q);
    }
    __syncthreads();
    if (threadIdx.x == 0) {
        __threadfence();
        islast = (atomicAdd(&g_cs_ticket[t], 1u) == gridDim.x - 1);
    }
    __syncthreads();
    if (islast && threadIdx.x < 64) {
        int o = t * 64 + threadIdx.x;
        float fs = atomicAdd(&g_colsum[o], 0.f);
        float fq = atomicAdd(&g_colsq[o], 0.f);
        float mean = fs * (1.f / NN);
        float var = (fq - fs * fs * (1.f / NN)) * (1.f / (NN - 1));
        g_mean[o] = mean;
        g_rinv[o] = 1.f / (sqrtf(fmaxf(var, 0.f)) + 1e-6f);
        g_colsum[o] = 0.f;
        g_colsq[o] = 0.f;
        if (threadIdx.x == 0) g_cs_ticket[t] = 0u;
    }
}

// ---------------- 2: normalize x (all T) + split weights ----------------
__global__ void k_prep(const float* __restrict__ xs,
                       const float* __restrict__ Wrel, const float* __restrict__ brel,
                       const float* __restrict__ Wroot, const float* __restrict__ Wg,
                       const float* __restrict__ bg) {
    int gid = blockIdx.x * blockDim.x + threadIdx.x;   // TT*NN*FF threads
    int t = gid / (NN * FF);
    int rem = gid - t * (NN * FF);
    int n = rem >> 6, f = rem & 63;
    float xn = (xs[gid] - g_mean[t * 64 + f]) * g_rinv[t * 64 + f];
    g_X[((long)t * NN + n) * KX + 64 + f] = xn;

    if (gid < KX * G4H) {
        int k = gid >> 8, col = gid & 255;
        int g = col >> 6, h2 = col & 63;
        float w = (k < 64) ? Wrel[g * 4096 + k * 64 + h2]
                           : Wroot[g * 4096 + (k - 64) * 64 + h2];
        float hi, lo;
        tf32split(w, hi, lo);
        g_Wx_hi[gid] = hi; g_Wx_lo[gid] = lo;
    }
    if (gid < KH * G4H) {
        int k = gid >> 8, col = gid & 255;
        int g = col >> 6, h2 = col & 63;
        float hi, lo;
        tf32split(Wg[g * 4096 + k * 64 + h2], hi, lo);
        g_Wg_hi[gid] = hi; g_Wg_lo[gid] = lo;
    }
    if (gid < G4H) g_bc[gid] = brel[gid] + bg[gid];
}

// ---------------- 3: prefix scan of counts (fast shfl scan) + norms ----------------
__global__ void k_prefix() {
    __shared__ int warpsum[32];
    __shared__ int carrysh;
    int t = threadIdx.x, lane = t & 31, wid = t >> 5;
    if (t == 0) carrysh = 0;
    __syncthreads();
    for (int c = 0; c < (NN + 1023) / 1024; c++) {
        int i = c * 1024 + t;
        int v = (i < NN) ? g_cnt[i] : 0;
        int x = v;
#pragma unroll
        for (int o = 1; o < 32; o <<= 1) {
            int y = __shfl_up_sync(0xffffffffu, x, o);
            if (lane >= o) x += y;
        }
        if (lane == 31) warpsum[wid] = x;
        __syncthreads();
        if (wid == 0) {
            int sv = warpsum[lane];
#pragma unroll
            for (int o = 1; o < 32; o <<= 1) {
                int y = __shfl_up_sync(0xffffffffu, sv, o);
                if (lane >= o) sv += y;
            }
            warpsum[lane] = sv;
        }
        __syncthreads();
        int incl = x + (wid > 0 ? warpsum[wid - 1] : 0);
        int base = carrysh;
        if (i < NN) {
            g_rowptr[i] = base + incl - v;
            float dd = (float)v + 1.f;
            g_dinv[i] = rsqrtf(dd);
            g_self[i] = 1.f / dd;
            g_cnt[i] = 0;   // reset for next replay
        }
        __syncthreads();
        if (t == 1023) carrysh = base + incl;
        __syncthreads();
    }
    if (t == 0) g_rowptr[NN] = carrysh;
}

// ---------------- 4: bucket edges by destination ----------------
__global__ void k_sortedges() {
    int e = blockIdx.x * blockDim.x + threadIdx.x;
    if (e >= EE) return;
    int s = g_src[e], d = g_dst[e];
    int pos = g_rowptr[d] + atomicAdd(&g_cursor[d], 1);
    g_s_src[pos] = s;
    g_s_eid[pos] = e;
    g_s_gcn[pos] = g_dinv[s] * g_dinv[d];
}

// ---------------- 5: batched agg_x gather (all T in one pass) ----------------
__global__ void k_xgather(const float* __restrict__ ea) {
    int node = (blockIdx.x * blockDim.x + threadIdx.x) >> 5;
    int lane = threadIdx.x & 31;
    if (node >= NN) return;
    int beg = g_rowptr[node], end = g_rowptr[node + 1];
    float2 a0 = {0.f, 0.f}, a1 = {0.f, 0.f}, a2 = {0.f, 0.f}, a3 = {0.f, 0.f};
    for (int e = beg; e < end; e++) {
        int s = g_s_src[e];
        int eid = g_s_eid[e];
        float w0 = ea[eid], w1 = ea[EE + eid], w2 = ea[2 * EE + eid], w3 = ea[3 * EE + eid];
        const float2* x0 = (const float2*)(g_X + ((long)s) * KX + 64);
        const float2* x1 = (const float2*)(g_X + ((long)(NN + s)) * KX + 64);
        const float2* x2 = (const float2*)(g_X + ((long)(2 * NN + s)) * KX + 64);
        const float2* x3 = (const float2*)(g_X + ((long)(3 * NN + s)) * KX + 64);
        float2 v0 = x0[lane], v1 = x1[lane], v2 = x2[lane], v3 = x3[lane];
        a0.x += w0 * v0.x; a0.y += w0 * v0.y;
        a1.x += w1 * v1.x; a1.y += w1 * v1.y;
        a2.x += w2 * v2.x; a2.y += w2 * v2.y;
        a3.x += w3 * v3.x; a3.y += w3 * v3.y;
    }
    ((float2*)(g_X + ((long)node) * KX))[lane] = a0;
    ((float2*)(g_X + ((long)(NN + node)) * KX))[lane] = a1;
    ((float2*)(g_X + ((long)(2 * NN + node)) * KX))[lane] = a2;
    ((float2*)(g_X + ((long)(3 * NN + node)) * KX))[lane] = a3;
}

// ---------------- 6: big batched GEMM  P = X[80000,128] @ Wx[128,256] ----------------
__global__ void __launch_bounds__(256) k_biggemm() {
    __shared__ float As_hi[64][18], As_lo[64][18];
    __shared__ float Bs_hi[BK][264], Bs_lo[BK][264];
    int tid = threadIdx.x;
    int lane = tid & 31, warp = tid >> 5;
    int wm = warp >> 2, wn = warp & 3;
    int gq = lane >> 2, tg = lane & 3;
    long r0 = (long)blockIdx.x * 64;

    float acc[2][4][2][4];
#pragma unroll
    for (int a = 0; a < 2; a++)
#pragma unroll
        for (int b = 0; b < 4; b++)
#pragma unroll
            for (int cc = 0; cc < 2; cc++)
#pragma unroll
                for (int d = 0; d < 4; d++) acc[a][b][cc][d] = 0.f;

    int arow = tid >> 2;
    int ac4 = (tid & 3) * 4;
    const float* Abase = g_X + (r0 + arow) * KX + ac4;

    for (int k0 = 0; k0 < KX; k0 += BK) {
        float4 av = *(const float4*)(Abase + k0);
        {
            float h, l;
            tf32split(av.x, h, l); As_hi[arow][ac4 + 0] = h; As_lo[arow][ac4 + 0] = l;
            tf32split(av.y, h, l); As_hi[arow][ac4 + 1] = h; As_lo[arow][ac4 + 1] = l;
            tf32split(av.z, h, l); As_hi[arow][ac4 + 2] = h; As_lo[arow][ac4 + 2] = l;
            tf32split(av.w, h, l); As_hi[arow][ac4 + 3] = h; As_lo[arow][ac4 + 3] = l;
        }
#pragma unroll
        for (int i = 0; i < 4; i++) {
            int flat = i * 256 + tid;
            int br = flat >> 6, bc4 = (flat & 63) * 4;
            float4 bh = *(const float4*)(g_Wx_hi + (long)(k0 + br) * G4H + bc4);
            float4 bl = *(const float4*)(g_Wx_lo + (long)(k0 + br) * G4H + bc4);
            Bs_hi[br][bc4 + 0] = bh.x; Bs_hi[br][bc4 + 1] = bh.y;
            Bs_hi[br][bc4 + 2] = bh.z; Bs_hi[br][bc4 + 3] = bh.w;
            Bs_lo[br][bc4 + 0] = bl.x; Bs_lo[br][bc4 + 1] = bl.y;
            Bs_lo[br][bc4 + 2] = bl.z; Bs_lo[br][bc4 + 3] = bl.w;
        }
        __syncthreads();
#pragma unroll
        for (int ks = 0; ks < 2; ks++) {
            unsigned ahi[2][4], alo[2][4];
#pragma unroll
            for (int mi = 0; mi < 2; mi++)
#pragma unroll
                for (int q = 0; q < 4; q++) {
                    int ar = wm * 32 + mi * 16 + gq + ((q & 1) << 3);
                    int acx = ks * 8 + tg + ((q >> 1) << 2);
                    ahi[mi][q] = __float_as_uint(As_hi[ar][acx]);
                    alo[mi][q] = __float_as_uint(As_lo[ar][acx]);
                }
#pragma unroll
            for (int gg = 0; gg < 4; gg++)
#pragma unroll
                for (int s = 0; s < 2; s++) {
                    int cb = gg * 64 + wn * 16 + s * 8 + gq;
                    int kr = ks * 8 + tg;
                    unsigned bh0 = __float_as_uint(Bs_hi[kr][cb]);
                    unsigned bh1 = __float_as_uint(Bs_hi[kr + 4][cb]);
                    unsigned bl0 = __float_as_uint(Bs_lo[kr][cb]);
                    unsigned bl1 = __float_as_uint(Bs_lo[kr + 4][cb]);
#pragma unroll
                    for (int mi = 0; mi < 2; mi++) {
                        float* C = acc[mi][gg][s];
                        MMA_TF32(C[0], C[1], C[2], C[3],
                                 alo[mi][0], alo[mi][1], alo[mi][2], alo[mi][3], bh0, bh1);
                        MMA_TF32(C[0], C[1], C[2], C[3],
                                 ahi[mi][0], ahi[mi][1], ahi[mi][2], ahi[mi][3], bl0, bl1);
                        MMA_TF32(C[0], C[1], C[2], C[3],
                                 ahi[mi][0], ahi[mi][1], ahi[mi][2], ahi[mi][3], bh0, bh1);
                    }
                }
        }
        __syncthreads();
    }
#pragma unroll
    for (int mi = 0; mi < 2; mi++)
#pragma unroll
        for (int gg = 0; gg < 4; gg++)
#pragma unroll
            for (int s = 0; s < 2; s++)
#pragma unroll
                for (int half = 0; half < 2; half++) {
                    long row = r0 + wm * 32 + mi * 16 + gq + half * 8;
                    int j = gg * 64 + wn * 16 + s * 8 + tg * 2;
                    float2 v = make_float2(acc[mi][gg][s][half * 2 + 0],
                                           acc[mi][gg][s][half * 2 + 1]);
                    *(float2*)(g_P + row * G4H + j) = v;
                }
}

// ---------------- loop: agg_h gather ----------------
__global__ void k_hgather() {
    int node = (blockIdx.x * blockDim.x + threadIdx.x) >> 5;
    int lane = threadIdx.x & 31;
    if (node >= NN) return;
    if (lane == 0) g_cursor[node] = 0;   // reset for next replay (idempotent)
    int beg = g_rowptr[node], end = g_rowptr[node + 1];
    float slf = g_self[node];
    float2 hv = ((const float2*)(g_h + (long)node * 64))[lane];
    float2 acc = make_float2(slf * hv.x, slf * hv.y);
    for (int e = beg; e < end; e++) {
        int s = g_s_src[e];
        float gn = g_s_gcn[e];
        float2 v = ((const float2*)(g_h + (long)s * 64))[lane];
        acc.x += gn * v.x;
        acc.y += gn * v.y;
    }
    ((float2*)(g_AH + (long)node * 64))[lane] = acc;
}

// ---------------- loop: gates = AH[NN,64]@Wg + P[t] + bc, fused cell ----------------
__global__ void __launch_bounds__(256) k_hgemm(int t) {
    __shared__ float As_hi[64][18], As_lo[64][18];
    __shared__ float Bs_hi[BK][264], Bs_lo[BK][264];
    __shared__ float sbc[256];
    int tid = threadIdx.x;
    int lane = tid & 31, warp = tid >> 5;
    int wm = warp >> 2, wn = warp & 3;
    int gq = lane >> 2, tg = lane & 3;
    int r0 = blockIdx.x * 64;
    sbc[tid] = g_bc[tid];

    float acc[2][4][2][4];
#pragma unroll
    for (int a = 0; a < 2; a++)
#pragma unroll
        for (int b = 0; b < 4; b++)
#pragma unroll
            for (int cc = 0; cc < 2; cc++)
#pragma unroll
                for (int d = 0; d < 4; d++) acc[a][b][cc][d] = 0.f;

    int arow = tid >> 2;
    int ac4 = (tid & 3) * 4;
    bool rowok = (r0 + arow) < NN;
    const float* Abase = g_AH + (long)(r0 + arow) * KH + ac4;

    for (int k0 = 0; k0 < KH; k0 += BK) {
        float4 av = rowok ? *(const float4*)(Abase + k0) : make_float4(0.f, 0.f, 0.f, 0.f);
        {
            float h, l;
            tf32split(av.x, h, l); As_hi[arow][ac4 + 0] = h; As_lo[arow][ac4 + 0] = l;
            tf32split(av.y, h, l); As_hi[arow][ac4 + 1] = h; As_lo[arow][ac4 + 1] = l;
            tf32split(av.z, h, l); As_hi[arow][ac4 + 2] = h; As_lo[arow][ac4 + 2] = l;
            tf32split(av.w, h, l); As_hi[arow][ac4 + 3] = h; As_lo[arow][ac4 + 3] = l;
        }
#pragma unroll
        for (int i = 0; i < 4; i++) {
            int flat = i * 256 + tid;
            int br = flat >> 6, bc4 = (flat & 63) * 4;
            float4 bh = *(const float4*)(g_Wg_hi + (long)(k0 + br) * G4H + bc4);
            float4 bl = *(const float4*)(g_Wg_lo + (long)(k0 + br) * G4H + bc4);
            Bs_hi[br][bc4 + 0] = bh.x; Bs_hi[br][bc4 + 1] = bh.y;
            Bs_hi[br][bc4 + 2] = bh.z; Bs_hi[br][bc4 + 3] = bh.w;
            Bs_lo[br][bc4 + 0] = bl.x; Bs_lo[br][bc4 + 1] = bl.y;
            Bs_lo[br][bc4 + 2] = bl.z; Bs_lo[br][bc4 + 3] = bl.w;
        }
        __syncthreads();
#pragma unroll
        for (int ks = 0; ks < 2; ks++) {
            unsigned ahi[2][4], alo[2][4];
#pragma unroll
            for (int mi = 0; mi < 2; mi++)
#pragma unroll
                for (int q = 0; q < 4; q++) {
                    int ar = wm * 32 + mi * 16 + gq + ((q & 1) << 3);
                    int acx = ks * 8 + tg + ((q >> 1) << 2);
                    ahi[mi][q] = __float_as_uint(As_hi[ar][acx]);
                    alo[mi][q] = __float_as_uint(As_lo[ar][acx]);
                }
#pragma unroll
            for (int gg = 0; gg < 4; gg++)
#pragma unroll
                for (int s = 0; s < 2; s++) {
                    int cb = gg * 64 + wn * 16 + s * 8 + gq;
                    int kr = ks * 8 + tg;
                    unsigned bh0 = __float_as_uint(Bs_hi[kr][cb]);
                    unsigned bh1 = __float_as_uint(Bs_hi[kr + 4][cb]);
                    unsigned bl0 = __float_as_uint(Bs_lo[kr][cb]);
                    unsigned bl1 = __float_as_uint(Bs_lo[kr + 4][cb]);
#pragma unroll
                    for (int mi = 0; mi < 2; mi++) {
                        float* C = acc[mi][gg][s];
                        MMA_TF32(C[0], C[1], C[2], C[3],
                                 alo[mi][0], alo[mi][1], alo[mi][2], alo[mi][3], bh0, bh1);
                        MMA_TF32(C[0], C[1], C[2], C[3],
                                 ahi[mi][0], ahi[mi][1], ahi[mi][2], ahi[mi][3], bl0, bl1);
                        MMA_TF32(C[0], C[1], C[2], C[3],
                                 ahi[mi][0], ahi[mi][1], ahi[mi][2], ahi[mi][3], bh0, bh1);
                    }
                }
        }
        __syncthreads();
    }

    // epilogue: + P[t] + bias, LSTM cell
#pragma unroll
    for (int mi = 0; mi < 2; mi++)
#pragma unroll
        for (int s = 0; s < 2; s++)
#pragma unroll
            for (int half = 0; half < 2; half++) {
                int row = r0 + wm * 32 + mi * 16 + gq + half * 8;
                if (row >= NN) continue;
                int j = wn * 16 + s * 8 + tg * 2;
                const float* Prow = g_P + ((long)t * NN + row) * G4H;
                float2 pi = *(const float2*)(Prow + j);
                float2 pf = *(const float2*)(Prow + 64 + j);
                float2 po = *(const float2*)(Prow + 128 + j);
                float2 pm = *(const float2*)(Prow + 192 + j);
                float2 cold = *(const float2*)(g_c + (long)row * 64 + j);
                float outc[2], outh[2];
#pragma unroll
                for (int cc = 0; cc < 2; cc++) {
                    int ri = half * 2 + cc;
                    float gi = acc[mi][0][s][ri] + (cc ? pi.y : pi.x) + sbc[j + cc];
                    float gf = acc[mi][1][s][ri] + (cc ? pf.y : pf.x) + sbc[64 + j + cc];
                    float go = acc[mi][2][s][ri] + (cc ? po.y : po.x) + sbc[128 + j + cc];
                    float gm = acc[mi][3][s][ri] + (cc ? pm.y : pm.x) + sbc[192 + j + cc];
                    float ii = sigm(gi), ff = sigm(gf), oo = sigm(go);
                    float mm = fmaxf(gm, 0.f);
                    float cv = tanhf(ii * mm + ff * (cc ? cold.y : cold.x));
                    outc[cc] = cv;
                    outh[cc] = oo * tanhf(cv);
                }
                *(float2*)(g_c + (long)row * 64 + j) = make_float2(outc[0], outc[1]);
                *(float2*)(g_h + (long)row * 64 + j) = make_float2(outh[0], outh[1]);
            }
}

// ---------------- DGPool ----------------
__global__ void k_vnorm(const float* __restrict__ pv) {
    __shared__ float red[64];
    int t = threadIdx.x;
    float v = pv[t];
    red[t] = v * v;
    __syncthreads();
    for (int s = 32; s > 0; s >>= 1) { if (t < s) red[t] += red[t + s]; __syncthreads(); }
    g_v[t] = v / (sqrtf(red[0]) + 1e-8f);
}

__global__ void k_scores() {
    __shared__ float ws[8];
    __shared__ int islast;
    int lane = threadIdx.x & 31, w = threadIdx.x >> 5;
    int n = blockIdx.x * 8 + w;
    float p = 0.f;
    if (n < NN)
        p = g_h[n * 64 + lane] * g_v[lane] + g_h[n * 64 + 32 + lane] * g_v[32 + lane];
    for (int o = 16; o; o >>= 1) p += __shfl_down_sync(0xffffffffu, p, o);
    if (lane == 0) {
        if (n < NN) g_raw[n] = p;
        ws[w] = (n < NN) ? p : 0.f;
    }
    __syncthreads();
    if (threadIdx.x == 0) {
        float s = 0.f, q = 0.f;
        for (int i = 0; i < 8; i++) { s += ws[i]; q += ws[i] * ws[i]; }
        atomicAdd(&g_ssum, s);
        atomicAdd(&g_ssq, q);
        __threadfence();
        islast = (atomicAdd(&g_sc_ticket, 1u) == gridDim.x - 1);
    }
    __syncthreads();
    if (islast && threadIdx.x == 0) {
        float fs = atomicAdd(&g_ssum, 0.f);
        float fq = atomicAdd(&g_ssq, 0.f);
        float mean = fs * (1.f / NN);
        float var = fq * (1.f / NN) - mean * mean;
        g_smean = mean;
        g_sinv = 1.f / (sqrtf(fmaxf(var, 0.f)) + 1e-8f);
        g_ssum = 0.f; g_ssq = 0.f; g_sc_ticket = 0u;
    }
}

__global__ void k_standardize(float* __restrict__ out) {
    int n = blockIdx.x * blockDim.x + threadIdx.x;
    float pl = 0.f;
    if (n < NN) {
        float s = (g_raw[n] - g_smean) * g_sinv;
        out[1 + n] = s;
        float sg = sigm(s);
        g_sig[n] = sg;
        unsigned u = __float_as_uint(s);
        u = (u & 0x80000000u) ? ~u : (u | 0x80000000u);
        g_key[n] = u;
        pl = sg * (1.f - sg);
    }
    for (int o = 16; o; o >>= 1) pl += __shfl_down_sync(0xffffffffu, pl, o);
    __shared__ float sred[8];
    if ((threadIdx.x & 31) == 0) sred[threadIdx.x >> 5] = pl;
    __syncthreads();
    if (threadIdx.x == 0) {
        float s = 0.f;
        for (int i = 0; i < 8; i++) s += sred[i];
        atomicAdd(&g_ploss, s);
    }
}

__global__ void k_histscan(int shift) {
    __shared__ unsigned sh[256];
    __shared__ int islast;
    sh[threadIdx.x] = 0u;
    __syncthreads();
    unsigned pref = g_prefix;
    int n = blockIdx.x * blockDim.x + threadIdx.x;
    if (n < NN) {
        unsigned k = g_key[n];
        bool cand = (shift == 24) || ((k >> (shift + 8)) == (pref >> (shift + 8)));
        if (cand) atomicAdd(&sh[(k >> shift) & 255u], 1u);
    }
    __syncthreads();
    if (sh[threadIdx.x]) atomicAdd(&g_hist[threadIdx.x], sh[threadIdx.x]);
    __syncthreads();
    if (threadIdx.x == 0) {
        __threadfence();
        islast = (atomicAdd(&g_h_ticket, 1u) == gridDim.x - 1);
    }
    __syncthreads();
    if (islast) {
        unsigned v = atomicAdd(&g_hist[threadIdx.x], 0u);
        sh[threadIdx.x] = v;
        g_hist[threadIdx.x] = 0u;
        __syncthreads();
        if (threadIdx.x == 0) {
            unsigned kk = (shift == 24) ? KSEL : g_kkleft;
            unsigned cum = 0u;
            for (int b = 255; b >= 0; b--) {
                unsigned c = sh[b];
                if (cum + c >= kk) {
                    g_prefix |= ((unsigned)b) << shift;
                    g_kkleft = kk - cum;
                    break;
                }
                cum += c;
            }
            g_h_ticket = 0u;
        }
    }
}

__global__ void k_sumhigh() {
    __shared__ float acc[64];
    if (threadIdx.x < 64) acc[threadIdx.x] = 0.f;
    __syncthreads();
    int lane = threadIdx.x & 31, w = threadIdx.x >> 5;
    int n = blockIdx.x * 8 + w;
    if (n < NN) {
        int inc = 0;
        if (lane == 0) {
            unsigned key = g_key[n], tau = g_prefix;
            if (key > tau) inc = 1;
            else if (key == tau) {
                unsigned tk = atomicAdd(&g_ticket, 1u);
                inc = (tk < g_kkleft) ? 1 : 0;
            }
        }
        inc = __shfl_sync(0xffffffffu, inc, 0);
        if (inc) {
            float sg = g_sig[n];
            atomicAdd(&acc[lane],      g_h[n * 64 + lane] * sg);
            atomicAdd(&acc[lane + 32], g_h[n * 64 + lane + 32] * sg);
        }
    }
    __syncthreads();
    if (threadIdx.x < 64) atomicAdd(&g_high[threadIdx.x], acc[threadIdx.x]);
}

// ---------------- raw-fMRI LSTM ----------------
__global__ void k_Ggemm(const float* __restrict__ Wih, const float* __restrict__ ts) {
    __shared__ float sW[32][65];
    __shared__ float sT[32][51];
    int r0 = blockIdx.y * 64;
    int kbeg = blockIdx.x * 313;
    int kend = min(NN, kbeg + 313);
    int tid = threadIdx.x;
    int r = tid & 63, tq = tid >> 6;
    float acc[13];
#pragma unroll
    for (int j = 0; j < 13; j++) acc[j] = 0.f;

    for (int k0 = kbeg; k0 < kend; k0 += 32) {
#pragma unroll
        for (int i = 0; i < 8; i++) {
            int flat = i * 256 + tid;
            int kk = flat & 31, rr = flat >> 5;
            int kg = k0 + kk;
            sW[kk][rr] = (kg < kend) ? Wih[(long)(r0 + rr) * NN + kg] : 0.f;
        }
#pragma unroll
        for (int i = 0; i < 7; i++) {
            int flat = i * 256 + tid;
            if (flat < 1600) {
                int kk = flat & 31, t = flat >> 5;
                int kg = k0 + kk;
                sT[kk][t] = (kg < kend) ? ts[(long)t * NN + kg] : 0.f;
            }
        }
        __syncthreads();
#pragma unroll
        for (int kk = 0; kk < 32; kk++) {
            float wv = sW[kk][r];
#pragma unroll
            for (int j = 0; j < 13; j++) {
                int t = tq + 4 * j;
                if (t < TSN) acc[j] += wv * sT[kk][t];
            }
        }
        __syncthreads();
    }
#pragma unroll
    for (int j = 0; j < 13; j++) {
        int t = tq + 4 * j;
        if (t < TSN) atomicAdd(&g_G[t * G4H + r0 + r], acc[j]);
    }
}

__global__ void k_lstm(const float* __restrict__ Whh, const float* __restrict__ bih,
                       const float* __restrict__ bhh) {
    __shared__ float sh[64], scc[64], sg[256];
    int r = threadIdx.x;
    float wr[64];
#pragma unroll
    for (int m = 0; m < 64; m++) wr[m] = Whh[r * 64 + m];
    float bias = bih[r] + bhh[r];
    if (r < 64) { sh[r] = 0.f; scc[r] = 0.f; }
    __syncthreads();
    for (int t = 0; t < TSN; t++) {
        float a0 = 0.f, a1 = 0.f, a2 = 0.f, a3 = 0.f;
#pragma unroll
        for (int m = 0; m < 64; m += 4) {
            a0 += wr[m] * sh[m];
            a1 += wr[m + 1] * sh[m + 1];
            a2 += wr[m + 2] * sh[m + 2];
            a3 += wr[m + 3] * sh[m + 3];
        }
        float gv = g_G[t * G4H + r];
        g_G[t * G4H + r] = 0.f;   // reset for next replay
        sg[r] = gv + bias + ((a0 + a1) + (a2 + a3));
        __syncthreads();
        if (r < 64) {
            float gi = sg[r], gf = sg[64 + r], gg = sg[128 + r], go = sg[192 + r];
            float c = sigm(gf) * scc[r] + sigm(gi) * tanhf(gg);
            scc[r] = c;
            sh[r] = sigm(go) * tanhf(c);
        }
        __syncthreads();
    }
    if (r < 64) g_hl[r] = sh[r];
}

// ---------------- fusion head (+global resets for next replay) ----------------
__global__ void k_final(const float* __restrict__ lng, const float* __restrict__ lnb,
                        const float* __restrict__ W1, const float* __restrict__ b1,
                        const float* __restrict__ W2, const float* __restrict__ b2,
                        float* __restrict__ out) {
    __shared__ float red[128], sf[128], sz[64];
    int tid = threadIdx.x;
    float x = (tid < 64) ? g_high[tid] * (1.f / KSEL) : g_hl[tid - 64];
    if (tid < 64) g_high[tid] = 0.f;    // reset
    red[tid] = x;
    __syncthreads();
    for (int s = 64; s > 0; s >>= 1) { if (tid < s) red[tid] += red[tid + s]; __syncthreads(); }
    float mean = red[0] * (1.f / 128.f);
    __syncthreads();
    float d = x - mean;
    red[tid] = d * d;
    __syncthreads();
    for (int s = 64; s > 0; s >>= 1) { if (tid < s) red[tid] += red[tid + s]; __syncthreads(); }
    float var = red[0] * (1.f / 128.f);
    float y = d * rsqrtf(var + 1e-5f) * lng[tid] + lnb[tid];
    __syncthreads();
    sf[tid] = y;
    __syncthreads();
    if (tid < 64) {
        float a = b1[tid];
        for (int j = 0; j < 128; j++) a += sf[j] * W1[j * 64 + tid];
        sz[tid] = fmaxf(a, 0.f);
    }
    __syncthreads();
    red[tid] = (tid < 64) ? sz[tid] * W2[tid] : 0.f;
    __syncthreads();
    for (int s = 64; s > 0; s >>= 1) { if (tid < s) red[tid] += red[tid + s]; __syncthreads(); }
    if (tid == 0) {
        out[0] = red[0] + b2[0];
        out[NN + 1] = g_ploss * (1.f / NN);
        g_ploss = 0.f;
        g_prefix = 0u;
        g_kkleft = KSEL;
        g_ticket = 0u;
    }
}

// ---------------- launch ----------------
extern "C" void kernel_launch(void* const* d_in, const int* in_sizes, int n_in,
                              void* d_out, int out_size) {
    const float* xs   = (const float*)d_in[0];
    const void*  ei   = d_in[1];
    const float* ea   = (const float*)d_in[2];
    const float* h0   = (const float*)d_in[3];
    const float* c0   = (const float*)d_in[4];
    const float* ts   = (const float*)d_in[5];
    const float* Wrel = (const float*)d_in[6];
    const float* brel = (const float*)d_in[7];
    const float* Wroot= (const float*)d_in[8];
    const float* Wg   = (const float*)d_in[9];
    const float* bg   = (const float*)d_in[10];
    const float* pool = (const float*)d_in[11];
    const float* lng  = (const float*)d_in[12];
    const float* lnb  = (const float*)d_in[13];
    const float* Wih  = (const float*)d_in[14];
    const float* Whh  = (const float*)d_in[15];
    const float* bih  = (const float*)d_in[16];
    const float* bhh  = (const float*)d_in[17];
    const float* W1   = (const float*)d_in[18];
    const float* b1   = (const float*)d_in[19];
    const float* W2   = (const float*)d_in[20];
    const float* b2   = (const float*)d_in[21];
    float* out = (float*)d_out;

    k_decode<<<EE / 256, 256>>>(ei, h0, c0);
    k_colstats<<<dim3(40, TT), 256>>>(xs);
    k_prep<<<(TT * NN * FF) / 256, 256>>>(xs, Wrel, brel, Wroot, Wg, bg);
    k_prefix<<<1, 1024>>>();
    k_sortedges<<<EE / 256, 256>>>();
    k_xgather<<<(NN * 32 + 255) / 256, 256>>>(ea);
    k_biggemm<<<(TT * NN) / 64, 256>>>();

    for (int t = 0; t < TT; t++) {
        k_hgather<<<(NN * 32 + 255) / 256, 256>>>();
        k_hgemm<<<(NN + 63) / 64, 256>>>(t);
    }

    k_vnorm<<<1, 64>>>(pool);
    k_scores<<<(NN + 7) / 8, 256>>>();
    k_standardize<<<(NN + 255) / 256, 256>>>(out);
    for (int p = 0; p < 4; p++) k_histscan<<<(NN + 255) / 256, 256>>>(24 - 8 * p);
    k_sumhigh<<<(NN + 7) / 8, 256>>>();

    k_Ggemm<<<dim3(64, 4), 256>>>(Wih, ts);
    k_lstm<<<1, 256>>>(Whh, bih, bhh);
    k_final<<<1, 128>>>(lng, lnb, W1, b1, W2, b2, out);
}

// round 7
// speedup vs baseline: 1.7651x; 1.5708x over previous
#include <cuda_runtime.h>
#include <cuda_bf16.h>
#include <stdint.h>

#define TT   4
#define NN   20000
#define EE   320000
#define FF   64
#define HH   64
#define TSN  50
#define G4H  256
#define KX   128     // aggx(64) | xn(64)
#define KH   64      // aggh
#define KSEL 10000
#define BK   16

// ---------------- device scratch (zero-initialized at load) ----------------
__device__ __align__(16) float g_X[(long)TT * NN * KX];
__device__ __align__(16) float g_P[(long)TT * NN * G4H];
__device__ __align__(16) float g_AH[NN * KH];
__device__ __align__(16) float g_h[NN * HH];
__device__ __align__(16) float g_c[NN * HH];
__device__ float g_dinv[NN];
__device__ float g_self[NN];
__device__ __align__(16) int g_cnt[NN];
__device__ int   g_cursor[NN];
__device__ int   g_rowptr[NN + 1];
__device__ int   g_src[EE];
__device__ int   g_dst[EE];
__device__ int   g_s_src[EE];
__device__ int   g_s_eid[EE];
__device__ float g_s_gcn[EE];
__device__ __align__(16) unsigned g_Wxp_hi[(KX / 2) * G4H];
__device__ __align__(16) unsigned g_Wxp_lo[(KX / 2) * G4H];
__device__ __align__(16) unsigned g_Wgp_hi[(KH / 2) * G4H];
__device__ __align__(16) unsigned g_Wgp_lo[(KH / 2) * G4H];
__device__ __align__(16) float g_bc[G4H];
__device__ float g_colsum[TT * FF];
__device__ float g_colsq[TT * FF];
__device__ float g_mean[TT * FF];
__device__ float g_rinv[TT * FF];
__device__ float g_v[HH];
__device__ float g_raw[NN];
__device__ float g_sig[NN];
__device__ unsigned g_key[NN];
__device__ float g_high[HH];
__device__ __align__(16) float g_G[TSN * G4H];
__device__ float g_hl[HH];
__device__ unsigned g_hist[256];
__device__ unsigned g_prefix;
__device__ unsigned g_kkleft;
__device__ unsigned g_ticket;
__device__ unsigned g_cs_ticket[TT];
__device__ unsigned g_h_ticket, g_sc_ticket;
__device__ float g_ssum, g_ssq, g_smean, g_sinv, g_ploss;

__device__ __forceinline__ float sigm(float x) { return 1.f / (1.f + expf(-x)); }

// split (a,b) into packed bf16x2 hi + lo (2-term bf16 split; drops only lo*lo ~2^-18)
__device__ __forceinline__ void bf16split2(float a, float b, unsigned& hi, unsigned& lo) {
    __nv_bfloat16 ah = __float2bfloat16_rn(a);
    __nv_bfloat16 bh = __float2bfloat16_rn(b);
    float ar = a - __bfloat162float(ah);
    float br = b - __bfloat162float(bh);
    __nv_bfloat162 H; H.x = ah; H.y = bh;
    __nv_bfloat162 L; L.x = __float2bfloat16_rn(ar); L.y = __float2bfloat16_rn(br);
    hi = *(unsigned*)&H;
    lo = *(unsigned*)&L;
}

#define MMA_BF16(c0, c1, c2, c3, a0, a1, a2, a3, b0, b1)                         \
    asm volatile("mma.sync.aligned.m16n8k16.row.col.f32.bf16.bf16.f32 "          \
                 "{%0,%1,%2,%3}, {%4,%5,%6,%7}, {%8,%9}, {%0,%1,%2,%3};"         \
                 : "+f"(c0), "+f"(c1), "+f"(c2), "+f"(c3)                        \
                 : "r"(a0), "r"(a1), "r"(a2), "r"(a3), "r"(b0), "r"(b1))

// ---------------- branch B0: decode edges (+count) + copy h0/c0 ----------------
__global__ void k_decode(const void* eiraw, const float* __restrict__ h0,
                         const float* __restrict__ c0) {
    int gid = blockIdx.x * blockDim.x + threadIdx.x;   // exactly EE threads
    const long long* p64 = (const long long*)eiraw;
    bool is64 = true;
#pragma unroll
    for (int j = 0; j < 8; j++) {
        long long v = p64[j];
        if (v < 0 || v >= NN) is64 = false;
    }
    int s, d;
    if (is64) { s = (int)p64[gid]; d = (int)p64[EE + gid]; }
    else { const int* p32 = (const int*)eiraw; s = p32[gid]; d = p32[EE + gid]; }
    s = min(max(s, 0), NN - 1);
    d = min(max(d, 0), NN - 1);
    g_src[gid] = s;
    g_dst[gid] = d;
    atomicAdd(&g_cnt[d], 1);
    for (int j = gid; j < NN * HH; j += EE) { g_h[j] = h0[j]; g_c[j] = c0[j]; }
}

// ---------------- branch B1: fast single-block prefix scan + node norms ----------------
__global__ void k_prefix() {
    __shared__ int wsum[32];
    int t = threadIdx.x, lane = t & 31, wid = t >> 5;
    int vals[20];
    int s = 0;
    if (t < 1000) {
        const int4* p = (const int4*)(g_cnt + t * 20);
#pragma unroll
        for (int i = 0; i < 5; i++) {
            int4 v = p[i];
            vals[i * 4 + 0] = v.x; vals[i * 4 + 1] = v.y;
            vals[i * 4 + 2] = v.z; vals[i * 4 + 3] = v.w;
            s += v.x + v.y + v.z + v.w;
        }
    }
    int x = s;
#pragma unroll
    for (int o = 1; o < 32; o <<= 1) {
        int y = __shfl_up_sync(0xffffffffu, x, o);
        if (lane >= o) x += y;
    }
    if (lane == 31) wsum[wid] = x;
    __syncthreads();
    if (wid == 0) {
        int sv = wsum[lane];
#pragma unroll
        for (int o = 1; o < 32; o <<= 1) {
            int y = __shfl_up_sync(0xffffffffu, sv, o);
            if (lane >= o) sv += y;
        }
        wsum[lane] = sv;
    }
    __syncthreads();
    int excl = x - s + (wid > 0 ? wsum[wid - 1] : 0);
    if (t < 1000) {
        int run = excl;
#pragma unroll
        for (int j = 0; j < 20; j++) {
            int idx = t * 20 + j;
            g_rowptr[idx] = run;
            int v = vals[j];
            run += v;
            float dd = (float)v + 1.f;
            g_dinv[idx] = rsqrtf(dd);
            g_self[idx] = 1.f / dd;
            g_cnt[idx] = 0;   // reset for next replay
        }
    }
    if (t == 1023) g_rowptr[NN] = excl;   // t>=1000 have s=0, excl=total
}

// ---------------- branch B2: bucket edges by destination ----------------
__global__ void k_sortedges() {
    int e = blockIdx.x * blockDim.x + threadIdx.x;
    if (e >= EE) return;
    int s = g_src[e], d = g_dst[e];
    int pos = g_rowptr[d] + atomicAdd(&g_cursor[d], 1);
    g_s_src[pos] = s;
    g_s_eid[pos] = e;
    g_s_gcn[pos] = g_dinv[s] * g_dinv[d];
}

// ---------------- main A0: per-timestep column stats ----------------
__global__ void k_colstats(const float* __restrict__ xs) {
    __shared__ float ss[256], sq[256];
    __shared__ int islast;
    int t = blockIdx.y;
    const float* xt = xs + (long)t * NN * FF;
    int f = threadIdx.x & 63, slot = threadIdx.x >> 6;
    float s = 0.f, q = 0.f;
    for (int n = blockIdx.x * 4 + slot; n < NN; n += gridDim.x * 4) {
        float v = xt[n * 64 + f];
        s += v; q += v * v;
    }
    ss[threadIdx.x] = s; sq[threadIdx.x] = q;
    __syncthreads();
    if (slot == 0) {
        s = ss[f] + ss[f + 64] + ss[f + 128] + ss[f + 192];
        q = sq[f] + sq[f + 64] + sq[f + 128] + sq[f + 192];
        atomicAdd(&g_colsum[t * 64 + f], s);
        atomicAdd(&g_colsq[t * 64 + f], q);
    }
    __syncthreads();
    if (threadIdx.x == 0) {
        __threadfence();
        islast = (atomicAdd(&g_cs_ticket[t], 1u) == gridDim.x - 1);
    }
    __syncthreads();
    if (islast && threadIdx.x < 64) {
        int o = t * 64 + threadIdx.x;
        float fs = atomicAdd(&g_colsum[o], 0.f);
        float fq = atomicAdd(&g_colsq[o], 0.f);
        float mean = fs * (1.f / NN);
        float var = (fq - fs * fs * (1.f / NN)) * (1.f / (NN - 1));
        g_mean[o] = mean;
        g_rinv[o] = 1.f / (sqrtf(fmaxf(var, 0.f)) + 1e-6f);
        g_colsum[o] = 0.f;
        g_colsq[o] = 0.f;
        if (threadIdx.x == 0) g_cs_ticket[t] = 0u;
    }
}

// ---------------- main A1: normalize x (all T) + pack/split weights ----------------
__global__ void k_prep(const float* __restrict__ xs,
                       const float* __restrict__ Wrel, const float* __restrict__ brel,
                       const float* __restrict__ Wroot, const float* __restrict__ Wg,
                       const float* __restrict__ bg) {
    int gid = blockIdx.x * blockDim.x + threadIdx.x;   // TT*NN*FF threads
    int t = gid / (NN * FF);
    int rem = gid - t * (NN * FF);
    int n = rem >> 6, f = rem & 63;
    float xn = (xs[gid] - g_mean[t * 64 + f]) * g_rinv[t * 64 + f];
    g_X[((long)t * NN + n) * KX + 64 + f] = xn;

    if (gid < (KX / 2) * G4H) {
        int kp = gid >> 8, col = gid & 255;
        int g = col >> 6, h2 = col & 63;
        int k0 = 2 * kp, k1 = 2 * kp + 1;
        float w0 = (k0 < 64) ? Wrel[g * 4096 + k0 * 64 + h2]
                             : Wroot[g * 4096 + (k0 - 64) * 64 + h2];
        float w1 = (k1 < 64) ? Wrel[g * 4096 + k1 * 64 + h2]
                             : Wroot[g * 4096 + (k1 - 64) * 64 + h2];
        unsigned hi, lo;
        bf16split2(w0, w1, hi, lo);
        g_Wxp_hi[gid] = hi; g_Wxp_lo[gid] = lo;
    }
    if (gid < (KH / 2) * G4H) {
        int kp = gid >> 8, col = gid & 255;
        int g = col >> 6, h2 = col & 63;
        unsigned hi, lo;
        bf16split2(Wg[g * 4096 + (2 * kp) * 64 + h2],
                   Wg[g * 4096 + (2 * kp + 1) * 64 + h2], hi, lo);
        g_Wgp_hi[gid] = hi; g_Wgp_lo[gid] = lo;
    }
    if (gid < G4H) g_bc[gid] = brel[gid] + bg[gid];
}

// ---------------- main A2: batched agg_x gather (all T in one pass) ----------------
__global__ void k_xgather(const float* __restrict__ ea) {
    int node = (blockIdx.x * blockDim.x + threadIdx.x) >> 5;
    int lane = threadIdx.x & 31;
    if (node >= NN) return;
    int beg = g_rowptr[node], end = g_rowptr[node + 1];
    float2 a0 = {0.f, 0.f}, a1 = {0.f, 0.f}, a2 = {0.f, 0.f}, a3 = {0.f, 0.f};
    for (int e = beg; e < end; e++) {
        int s = g_s_src[e];
        int eid = g_s_eid[e];
        float w0 = ea[eid], w1 = ea[EE + eid], w2 = ea[2 * EE + eid], w3 = ea[3 * EE + eid];
        float2 v0 = ((const float2*)(g_X + ((long)s) * KX + 64))[lane];
        float2 v1 = ((const float2*)(g_X + ((long)(NN + s)) * KX + 64))[lane];
        float2 v2 = ((const float2*)(g_X + ((long)(2 * NN + s)) * KX + 64))[lane];
        float2 v3 = ((const float2*)(g_X + ((long)(3 * NN + s)) * KX + 64))[lane];
        a0.x += w0 * v0.x; a0.y += w0 * v0.y;
        a1.x += w1 * v1.x; a1.y += w1 * v1.y;
        a2.x += w2 * v2.x; a2.y += w2 * v2.y;
        a3.x += w3 * v3.x; a3.y += w3 * v3.y;
    }
    ((float2*)(g_X + ((long)node) * KX))[lane] = a0;
    ((float2*)(g_X + ((long)(NN + node)) * KX))[lane] = a1;
    ((float2*)(g_X + ((long)(2 * NN + node)) * KX))[lane] = a2;
    ((float2*)(g_X + ((long)(3 * NN + node)) * KX))[lane] = a3;
}

// ---------------- main A3: big batched GEMM  P = X[80000,128] @ Wx[128,256] (3xBF16) ----------------
__global__ void __launch_bounds__(256) k_biggemm() {
    __shared__ unsigned Ah[64][12], Al[64][12];
    __shared__ unsigned Bh[8][264], Bl[8][264];
    int tid = threadIdx.x;
    int lane = tid & 31, warp = tid >> 5;
    int wm = warp >> 2, wn = warp & 3;
    int gq = lane >> 2, tg = lane & 3;
    long r0 = (long)blockIdx.x * 64;

    float acc[2][4][2][4];
#pragma unroll
    for (int a = 0; a < 2; a++)
#pragma unroll
        for (int b = 0; b < 4; b++)
#pragma unroll
            for (int cc = 0; cc < 2; cc++)
#pragma unroll
                for (int d = 0; d < 4; d++) acc[a][b][cc][d] = 0.f;

    int arow = tid >> 2;
    int ac4 = (tid & 3) * 4;
    int akp = (tid & 3) * 2;
    const float* Abase = g_X + (r0 + arow) * KX + ac4;

    for (int k0 = 0; k0 < KX; k0 += BK) {
        float4 av = *(const float4*)(Abase + k0);
        unsigned h0, l0, h1, l1;
        bf16split2(av.x, av.y, h0, l0);
        bf16split2(av.z, av.w, h1, l1);
        Ah[arow][akp] = h0; Ah[arow][akp + 1] = h1;
        Al[arow][akp] = l0; Al[arow][akp + 1] = l1;
        int kp0 = (k0 >> 1);   // global packed row base
#pragma unroll
        for (int i = 0; i < 2; i++) {
            int flat4 = i * 256 + tid;            // 512 uint4 = 2048 u32
            int kpl = flat4 >> 6, c4 = (flat4 & 63) * 4;
            uint4 bh = *(const uint4*)(g_Wxp_hi + (kp0 + kpl) * G4H + c4);
            uint4 bl = *(const uint4*)(g_Wxp_lo + (kp0 + kpl) * G4H + c4);
            Bh[kpl][c4 + 0] = bh.x; Bh[kpl][c4 + 1] = bh.y;
            Bh[kpl][c4 + 2] = bh.z; Bh[kpl][c4 + 3] = bh.w;
            Bl[kpl][c4 + 0] = bl.x; Bl[kpl][c4 + 1] = bl.y;
            Bl[kpl][c4 + 2] = bl.z; Bl[kpl][c4 + 3] = bl.w;
        }
        __syncthreads();

        unsigned ahi[2][4], alo[2][4];
#pragma unroll
        for (int mi = 0; mi < 2; mi++) {
            int rb = wm * 32 + mi * 16;
            ahi[mi][0] = Ah[rb + gq][tg];     alo[mi][0] = Al[rb + gq][tg];
            ahi[mi][1] = Ah[rb + gq + 8][tg]; alo[mi][1] = Al[rb + gq + 8][tg];
            ahi[mi][2] = Ah[rb + gq][tg + 4]; alo[mi][2] = Al[rb + gq][tg + 4];
            ahi[mi][3] = Ah[rb + gq + 8][tg + 4]; alo[mi][3] = Al[rb + gq + 8][tg + 4];
        }
#pragma unroll
        for (int gg = 0; gg < 4; gg++)
#pragma unroll
            for (int s = 0; s < 2; s++) {
                int cb = gg * 64 + wn * 16 + s * 8 + gq;
                unsigned bh0 = Bh[tg][cb], bh1 = Bh[tg + 4][cb];
                unsigned bl0 = Bl[tg][cb], bl1 = Bl[tg + 4][cb];
#pragma unroll
                for (int mi = 0; mi < 2; mi++) {
                    float* C = acc[mi][gg][s];
                    MMA_BF16(C[0], C[1], C[2], C[3],
                             alo[mi][0], alo[mi][1], alo[mi][2], alo[mi][3], bh0, bh1);
                    MMA_BF16(C[0], C[1], C[2], C[3],
                             ahi[mi][0], ahi[mi][1], ahi[mi][2], ahi[mi][3], bl0, bl1);
                    MMA_BF16(C[0], C[1], C[2], C[3],
                             ahi[mi][0], ahi[mi][1], ahi[mi][2], ahi[mi][3], bh0, bh1);
                }
            }
        __syncthreads();
    }
#pragma unroll
    for (int mi = 0; mi < 2; mi++)
#pragma unroll
        for (int gg = 0; gg < 4; gg++)
#pragma unroll
            for (int s = 0; s < 2; s++)
#pragma unroll
                for (int half = 0; half < 2; half++) {
                    long row = r0 + wm * 32 + mi * 16 + gq + half * 8;
                    int j = gg * 64 + wn * 16 + s * 8 + tg * 2;
                    float2 v = make_float2(acc[mi][gg][s][half * 2 + 0],
                                           acc[mi][gg][s][half * 2 + 1]);
                    *(float2*)(g_P + row * G4H + j) = v;
                }
}

// ---------------- loop: agg_h gather ----------------
__global__ void k_hgather() {
    int node = (blockIdx.x * blockDim.x + threadIdx.x) >> 5;
    int lane = threadIdx.x & 31;
    if (node >= NN) return;
    if (lane == 0) g_cursor[node] = 0;   // reset for next replay (idempotent)
    int beg = g_rowptr[node], end = g_rowptr[node + 1];
    float slf = g_self[node];
    float2 hv = ((const float2*)(g_h + (long)node * 64))[lane];
    float2 acc = make_float2(slf * hv.x, slf * hv.y);
    for (int e = beg; e < end; e++) {
        int s = g_s_src[e];
        float gn = g_s_gcn[e];
        float2 v = ((const float2*)(g_h + (long)s * 64))[lane];
        acc.x += gn * v.x;
        acc.y += gn * v.y;
    }
    ((float2*)(g_AH + (long)node * 64))[lane] = acc;
}

// ---------------- loop: gates = AH[NN,64]@Wg + P[t] + bc, fused cell (3xBF16) ----------------
__global__ void __launch_bounds__(256) k_hgemm(int t) {
    __shared__ unsigned Ah[64][12], Al[64][12];
    __shared__ unsigned Bh[8][264], Bl[8][264];
    __shared__ float sbc[256];
    int tid = threadIdx.x;
    int lane = tid & 31, warp = tid >> 5;
    int wm = warp >> 2, wn = warp & 3;
    int gq = lane >> 2, tg = lane & 3;
    int r0 = blockIdx.x * 64;
    sbc[tid] = g_bc[tid];

    float acc[2][4][2][4];
#pragma unroll
    for (int a = 0; a < 2; a++)
#pragma unroll
        for (int b = 0; b < 4; b++)
#pragma unroll
            for (int cc = 0; cc < 2; cc++)
#pragma unroll
                for (int d = 0; d < 4; d++) acc[a][b][cc][d] = 0.f;

    int arow = tid >> 2;
    int ac4 = (tid & 3) * 4;
    int akp = (tid & 3) * 2;
    bool rowok = (r0 + arow) < NN;
    const float* Abase = g_AH + (long)(r0 + arow) * KH + ac4;

    for (int k0 = 0; k0 < KH; k0 += BK) {
        float4 av = rowok ? *(const float4*)(Abase + k0) : make_float4(0.f, 0.f, 0.f, 0.f);
        unsigned h0, l0, h1, l1;
        bf16split2(av.x, av.y, h0, l0);
        bf16split2(av.z, av.w, h1, l1);
        Ah[arow][akp] = h0; Ah[arow][akp + 1] = h1;
        Al[arow][akp] = l0; Al[arow][akp + 1] = l1;
        int kp0 = (k0 >> 1);
#pragma unroll
        for (int i = 0; i < 2; i++) {
            int flat4 = i * 256 + tid;
            int kpl = flat4 >> 6, c4 = (flat4 & 63) * 4;
            uint4 bh = *(const uint4*)(g_Wgp_hi + (kp0 + kpl) * G4H + c4);
            uint4 bl = *(const uint4*)(g_Wgp_lo + (kp0 + kpl) * G4H + c4);
            Bh[kpl][c4 + 0] = bh.x; Bh[kpl][c4 + 1] = bh.y;
            Bh[kpl][c4 + 2] = bh.z; Bh[kpl][c4 + 3] = bh.w;
            Bl[kpl][c4 + 0] = bl.x; Bl[kpl][c4 + 1] = bl.y;
            Bl[kpl][c4 + 2] = bl.z; Bl[kpl][c4 + 3] = bl.w;
        }
        __syncthreads();

        unsigned ahi[2][4], alo[2][4];
#pragma unroll
        for (int mi = 0; mi < 2; mi++) {
            int rb = wm * 32 + mi * 16;
            ahi[mi][0] = Ah[rb + gq][tg];     alo[mi][0] = Al[rb + gq][tg];
            ahi[mi][1] = Ah[rb + gq + 8][tg]; alo[mi][1] = Al[rb + gq + 8][tg];
            ahi[mi][2] = Ah[rb + gq][tg + 4]; alo[mi][2] = Al[rb + gq][tg + 4];
            ahi[mi][3] = Ah[rb + gq + 8][tg + 4]; alo[mi][3] = Al[rb + gq + 8][tg + 4];
        }
#pragma unroll
        for (int gg = 0; gg < 4; gg++)
#pragma unroll
            for (int s = 0; s < 2; s++) {
                int cb = gg * 64 + wn * 16 + s * 8 + gq;
                unsigned bh0 = Bh[tg][cb], bh1 = Bh[tg + 4][cb];
                unsigned bl0 = Bl[tg][cb], bl1 = Bl[tg + 4][cb];
#pragma unroll
                for (int mi = 0; mi < 2; mi++) {
                    float* C = acc[mi][gg][s];
                    MMA_BF16(C[0], C[1], C[2], C[3],
                             alo[mi][0], alo[mi][1], alo[mi][2], alo[mi][3], bh0, bh1);
                    MMA_BF16(C[0], C[1], C[2], C[3],
                             ahi[mi][0], ahi[mi][1], ahi[mi][2], ahi[mi][3], bl0, bl1);
                    MMA_BF16(C[0], C[1], C[2], C[3],
                             ahi[mi][0], ahi[mi][1], ahi[mi][2], ahi[mi][3], bh0, bh1);
                }
            }
        __syncthreads();
    }

    // epilogue: + P[t] + bias, LSTM cell
#pragma unroll
    for (int mi = 0; mi < 2; mi++)
#pragma unroll
        for (int s = 0; s < 2; s++)
#pragma unroll
            for (int half = 0; half < 2; half++) {
                int row = r0 + wm * 32 + mi * 16 + gq + half * 8;
                if (row >= NN) continue;
                int j = wn * 16 + s * 8 + tg * 2;
                const float* Prow = g_P + ((long)t * NN + row) * G4H;
                float2 pi = *(const float2*)(Prow + j);
                float2 pf = *(const float2*)(Prow + 64 + j);
                float2 po = *(const float2*)(Prow + 128 + j);
                float2 pm = *(const float2*)(Prow + 192 + j);
                float2 cold = *(const float2*)(g_c + (long)row * 64 + j);
                float outc[2], outh[2];
#pragma unroll
                for (int cc = 0; cc < 2; cc++) {
                    int ri = half * 2 + cc;
                    float gi = acc[mi][0][s][ri] + (cc ? pi.y : pi.x) + sbc[j + cc];
                    float gf = acc[mi][1][s][ri] + (cc ? pf.y : pf.x) + sbc[64 + j + cc];
                    float go = acc[mi][2][s][ri] + (cc ? po.y : po.x) + sbc[128 + j + cc];
                    float gm = acc[mi][3][s][ri] + (cc ? pm.y : pm.x) + sbc[192 + j + cc];
                    float ii = sigm(gi), ff = sigm(gf), oo = sigm(go);
                    float mm = fmaxf(gm, 0.f);
                    float cv = tanhf(ii * mm + ff * (cc ? cold.y : cold.x));
                    outc[cc] = cv;
                    outh[cc] = oo * tanhf(cv);
                }
                *(float2*)(g_c + (long)row * 64 + j) = make_float2(outc[0], outc[1]);
                *(float2*)(g_h + (long)row * 64 + j) = make_float2(outh[0], outh[1]);
            }
}

// ---------------- DGPool ----------------
__global__ void k_vnorm(const float* __restrict__ pv) {
    __shared__ float red[64];
    int t = threadIdx.x;
    float v = pv[t];
    red[t] = v * v;
    __syncthreads();
    for (int s = 32; s > 0; s >>= 1) { if (t < s) red[t] += red[t + s]; __syncthreads(); }
    g_v[t] = v / (sqrtf(red[0]) + 1e-8f);
}

__global__ void k_scores() {
    __shared__ float ws[8];
    __shared__ int islast;
    int lane = threadIdx.x & 31, w = threadIdx.x >> 5;
    int n = blockIdx.x * 8 + w;
    float p = 0.f;
    if (n < NN)
        p = g_h[n * 64 + lane] * g_v[lane] + g_h[n * 64 + 32 + lane] * g_v[32 + lane];
    for (int o = 16; o; o >>= 1) p += __shfl_down_sync(0xffffffffu, p, o);
    if (lane == 0) {
        if (n < NN) g_raw[n] = p;
        ws[w] = (n < NN) ? p : 0.f;
    }
    __syncthreads();
    if (threadIdx.x == 0) {
        float s = 0.f, q = 0.f;
        for (int i = 0; i < 8; i++) { s += ws[i]; q += ws[i] * ws[i]; }
        atomicAdd(&g_ssum, s);
        atomicAdd(&g_ssq, q);
        __threadfence();
        islast = (atomicAdd(&g_sc_ticket, 1u) == gridDim.x - 1);
    }
    __syncthreads();
    if (islast && threadIdx.x == 0) {
        float fs = atomicAdd(&g_ssum, 0.f);
        float fq = atomicAdd(&g_ssq, 0.f);
        float mean = fs * (1.f / NN);
        float var = fq * (1.f / NN) - mean * mean;
        g_smean = mean;
        g_sinv = 1.f / (sqrtf(fmaxf(var, 0.f)) + 1e-8f);
        g_ssum = 0.f; g_ssq = 0.f; g_sc_ticket = 0u;
    }
}

__global__ void k_standardize(float* __restrict__ out) {
    int n = blockIdx.x * blockDim.x + threadIdx.x;
    float pl = 0.f;
    if (n < NN) {
        float s = (g_raw[n] - g_smean) * g_sinv;
        out[1 + n] = s;
        float sg = sigm(s);
        g_sig[n] = sg;
        unsigned u = __float_as_uint(s);
        u = (u & 0x80000000u) ? ~u : (u | 0x80000000u);
        g_key[n] = u;
        pl = sg * (1.f - sg);
    }
    for (int o = 16; o; o >>= 1) pl += __shfl_down_sync(0xffffffffu, pl, o);
    __shared__ float sred[8];
    if ((threadIdx.x & 31) == 0) sred[threadIdx.x >> 5] = pl;
    __syncthreads();
    if (threadIdx.x == 0) {
        float s = 0.f;
        for (int i = 0; i < 8; i++) s += sred[i];
        atomicAdd(&g_ploss, s);
    }
}

__global__ void k_histscan(int shift) {
    __shared__ unsigned sh[256];
    __shared__ int islast;
    sh[threadIdx.x] = 0u;
    __syncthreads();
    unsigned pref = g_prefix;
    int n = blockIdx.x * blockDim.x + threadIdx.x;
    if (n < NN) {
        unsigned k = g_key[n];
        bool cand = (shift == 24) || ((k >> (shift + 8)) == (pref >> (shift + 8)));
        if (cand) atomicAdd(&sh[(k >> shift) & 255u], 1u);
    }
    __syncthreads();
    if (sh[threadIdx.x]) atomicAdd(&g_hist[threadIdx.x], sh[threadIdx.x]);
    __syncthreads();
    if (threadIdx.x == 0) {
        __threadfence();
        islast = (atomicAdd(&g_h_ticket, 1u) == gridDim.x - 1);
    }
    __syncthreads();
    if (islast) {
        unsigned v = atomicAdd(&g_hist[threadIdx.x], 0u);
        sh[threadIdx.x] = v;
        g_hist[threadIdx.x] = 0u;
        __syncthreads();
        if (threadIdx.x == 0) {
            unsigned kk = (shift == 24) ? KSEL : g_kkleft;
            unsigned cum = 0u;
            for (int b = 255; b >= 0; b--) {
                unsigned c = sh[b];
                if (cum + c >= kk) {
                    g_prefix |= ((unsigned)b) << shift;
                    g_kkleft = kk - cum;
                    break;
                }
                cum += c;
            }
            g_h_ticket = 0u;
        }
    }
}

__global__ void k_sumhigh() {
    __shared__ float acc[64];
    if (threadIdx.x < 64) acc[threadIdx.x] = 0.f;
    __syncthreads();
    int lane = threadIdx.x & 31, w = threadIdx.x >> 5;
    int n = blockIdx.x * 8 + w;
    if (n < NN) {
        int inc = 0;
        if (lane == 0) {
            unsigned key = g_key[n], tau = g_prefix;
            if (key > tau) inc = 1;
            else if (key == tau) {
                unsigned tk = atomicAdd(&g_ticket, 1u);
                inc = (tk < g_kkleft) ? 1 : 0;
            }
        }
        inc = __shfl_sync(0xffffffffu, inc, 0);
        if (inc) {
            float sg = g_sig[n];
            atomicAdd(&acc[lane],      g_h[n * 64 + lane] * sg);
            atomicAdd(&acc[lane + 32], g_h[n * 64 + lane + 32] * sg);
        }
    }
    __syncthreads();
    if (threadIdx.x < 64) atomicAdd(&g_high[threadIdx.x], acc[threadIdx.x]);
}

// ---------------- branch C: raw-fMRI LSTM ----------------
__global__ void k_Ggemm(const float* __restrict__ Wih, const float* __restrict__ ts) {
    __shared__ float sW[32][65];
    __shared__ float sT[32][51];
    int r0 = blockIdx.y * 64;
    int kbeg = blockIdx.x * 313;
    int kend = min(NN, kbeg + 313);
    int tid = threadIdx.x;
    int r = tid & 63, tq = tid >> 6;
    float acc[13];
#pragma unroll
    for (int j = 0; j < 13; j++) acc[j] = 0.f;

    for (int k0 = kbeg; k0 < kend; k0 += 32) {
#pragma unroll
        for (int i = 0; i < 8; i++) {
            int flat = i * 256 + tid;
            int kk = flat & 31, rr = flat >> 5;
            int kg = k0 + kk;
            sW[kk][rr] = (kg < kend) ? Wih[(long)(r0 + rr) * NN + kg] : 0.f;
        }
#pragma unroll
        for (int i = 0; i < 7; i++) {
            int flat = i * 256 + tid;
            if (flat < 1600) {
                int kk = flat & 31, t = flat >> 5;
                int kg = k0 + kk;
                sT[kk][t] = (kg < kend) ? ts[(long)t * NN + kg] : 0.f;
            }
        }
        __syncthreads();
#pragma unroll
        for (int kk = 0; kk < 32; kk++) {
            float wv = sW[kk][r];
#pragma unroll
            for (int j = 0; j < 13; j++) {
                int t = tq + 4 * j;
                if (t < TSN) acc[j] += wv * sT[kk][t];
            }
        }
        __syncthreads();
    }
#pragma unroll
    for (int j = 0; j < 13; j++) {
        int t = tq + 4 * j;
        if (t < TSN) atomicAdd(&g_G[t * G4H + r0 + r], acc[j]);
    }
}

__global__ void k_lstm(const float* __restrict__ Whh, const float* __restrict__ bih,
                       const float* __restrict__ bhh) {
    __shared__ float sh[64], scc[64], sg[256];
    int r = threadIdx.x;
    float wr[64];
#pragma unroll
    for (int m = 0; m < 64; m++) wr[m] = Whh[r * 64 + m];
    float bias = bih[r] + bhh[r];
    if (r < 64) { sh[r] = 0.f; scc[r] = 0.f; }
    __syncthreads();
    for (int t = 0; t < TSN; t++) {
        float a0 = 0.f, a1 = 0.f, a2 = 0.f, a3 = 0.f;
#pragma unroll
        for (int m = 0; m < 64; m += 4) {
            a0 += wr[m] * sh[m];
            a1 += wr[m + 1] * sh[m + 1];
            a2 += wr[m + 2] * sh[m + 2];
            a3 += wr[m + 3] * sh[m + 3];
        }
        float gv = g_G[t * G4H + r];
        g_G[t * G4H + r] = 0.f;   // reset for next replay
        sg[r] = gv + bias + ((a0 + a1) + (a2 + a3));
        __syncthreads();
        if (r < 64) {
            float gi = sg[r], gf = sg[64 + r], gg = sg[128 + r], go = sg[192 + r];
            float c = sigm(gf) * scc[r] + sigm(gi) * tanhf(gg);
            scc[r] = c;
            sh[r] = sigm(go) * tanhf(c);
        }
        __syncthreads();
    }
    if (r < 64) g_hl[r] = sh[r];
}

// ---------------- fusion head (+global resets for next replay) ----------------
__global__ void k_final(const float* __restrict__ lng, const float* __restrict__ lnb,
                        const float* __restrict__ W1, const float* __restrict__ b1,
                        const float* __restrict__ W2, const float* __restrict__ b2,
                        float* __restrict__ out) {
    __shared__ float red[128], sf[128], sz[64];
    int tid = threadIdx.x;
    float x = (tid < 64) ? g_high[tid] * (1.f / KSEL) : g_hl[tid - 64];
    if (tid < 64) g_high[tid] = 0.f;    // reset
    red[tid] = x;
    __syncthreads();
    for (int s = 64; s > 0; s >>= 1) { if (tid < s) red[tid] += red[tid + s]; __syncthreads(); }
    float mean = red[0] * (1.f / 128.f);
    __syncthreads();
    float d = x - mean;
    red[tid] = d * d;
    __syncthreads();
    for (int s = 64; s > 0; s >>= 1) { if (tid < s) red[tid] += red[tid + s]; __syncthreads(); }
    float var = red[0] * (1.f / 128.f);
    float y = d * rsqrtf(var + 1e-5f) * lng[tid] + lnb[tid];
    __syncthreads();
    sf[tid] = y;
    __syncthreads();
    if (tid < 64) {
        float a = b1[tid];
        for (int j = 0; j < 128; j++) a += sf[j] * W1[j * 64 + tid];
        sz[tid] = fmaxf(a, 0.f);
    }
    __syncthreads();
    red[tid] = (tid < 64) ? sz[tid] * W2[tid] : 0.f;
    __syncthreads();
    for (int s = 64; s > 0; s >>= 1) { if (tid < s) red[tid] += red[tid + s]; __syncthreads(); }
    if (tid == 0) {
        out[0] = red[0] + b2[0];
        out[NN + 1] = g_ploss * (1.f / NN);
        g_ploss = 0.f;
        g_prefix = 0u;
        g_kkleft = KSEL;
        g_ticket = 0u;
    }
}

// ---------------- launch (forked graph; streams/events created ONCE) ----------------
extern "C" void kernel_launch(void* const* d_in, const int* in_sizes, int n_in,
                              void* d_out, int out_size) {
    const float* xs   = (const float*)d_in[0];
    const void*  ei   = d_in[1];
    const float* ea   = (const float*)d_in[2];
    const float* h0   = (const float*)d_in[3];
    const float* c0   = (const float*)d_in[4];
    const float* ts   = (const float*)d_in[5];
    const float* Wrel = (const float*)d_in[6];
    const float* brel = (const float*)d_in[7];
    const float* Wroot= (const float*)d_in[8];
    const float* Wg   = (const float*)d_in[9];
    const float* bg   = (const float*)d_in[10];
    const float* pool = (const float*)d_in[11];
    const float* lng  = (const float*)d_in[12];
    const float* lnb  = (const float*)d_in[13];
    const float* Wih  = (const float*)d_in[14];
    const float* Whh  = (const float*)d_in[15];
    const float* bih  = (const float*)d_in[16];
    const float* bhh  = (const float*)d_in[17];
    const float* W1   = (const float*)d_in[18];
    const float* b1   = (const float*)d_in[19];
    const float* W2   = (const float*)d_in[20];
    const float* b2   = (const float*)d_in[21];
    float* out = (float*)d_out;

    // Created once on the first (correctness) call — before the harness's
    // pre-capture memory baseline — and reused for every subsequent call,
    // so no allocation happens during capture/replay and nothing leaks
    // relative to the baseline.
    static cudaStream_t sB = nullptr, sC = nullptr;
    static cudaEvent_t evFork = nullptr, evEdges = nullptr, evLstm = nullptr;
    if (sB == nullptr) {
        cudaStreamCreateWithFlags(&sB, cudaStreamNonBlocking);
        cudaStreamCreateWithFlags(&sC, cudaStreamNonBlocking);
        cudaEventCreateWithFlags(&evFork, cudaEventDisableTiming);
        cudaEventCreateWithFlags(&evEdges, cudaEventDisableTiming);
        cudaEventCreateWithFlags(&evLstm, cudaEventDisableTiming);
    }

    cudaEventRecord(evFork, 0);
    cudaStreamWaitEvent(sB, evFork, 0);
    cudaStreamWaitEvent(sC, evFork, 0);

    // branch B: edge structure + h/c init
    k_decode<<<EE / 256, 256, 0, sB>>>(ei, h0, c0);
    k_prefix<<<1, 1024, 0, sB>>>();
    k_sortedges<<<EE / 256, 256, 0, sB>>>();
    cudaEventRecord(evEdges, sB);

    // branch C: fMRI LSTM (independent until k_final)
    k_Ggemm<<<dim3(64, 4), 256, 0, sC>>>(Wih, ts);
    k_lstm<<<1, 256, 0, sC>>>(Whh, bih, bhh);
    cudaEventRecord(evLstm, sC);

    // main branch
    k_colstats<<<dim3(40, TT), 256>>>(xs);
    k_prep<<<(TT * NN * FF) / 256, 256>>>(xs, Wrel, brel, Wroot, Wg, bg);
    cudaStreamWaitEvent(0, evEdges, 0);
    k_xgather<<<(NN * 32 + 255) / 256, 256>>>(ea);
    k_biggemm<<<(TT * NN) / 64, 256>>>();

    for (int t = 0; t < TT; t++) {
        k_hgather<<<(NN * 32 + 255) / 256, 256>>>();
        k_hgemm<<<(NN + 63) / 64, 256>>>(t);
    }

    k_vnorm<<<1, 64>>>(pool);
    k_scores<<<(NN + 7) / 8, 256>>>();
    k_standardize<<<(NN + 255) / 256, 256>>>(out);
    for (int p = 0; p < 4; p++) k_histscan<<<(NN + 255) / 256, 256>>>(24 - 8 * p);
    k_sumhigh<<<(NN + 7) / 8, 256>>>();

    cudaStreamWaitEvent(0, evLstm, 0);
    k_final<<<1, 128>>>(lng, lnb, W1, b1, W2, b2, out);
}

// round 8
// speedup vs baseline: 1.8821x; 1.0663x over previous
#include <cuda_runtime.h>
#include <cuda_bf16.h>
#include <stdint.h>

#define TT   4
#define NN   20000
#define EE   320000
#define FF   64
#define HH   64
#define TSN  50
#define G4H  256
#define KX   128     // aggx(64) | xn(64)
#define KH   64      // aggh
#define KSEL 10000
#define BK   16
#define KCH  157     // Ggemm K-chunk: 128 splits * 157 >= 20000

// ---------------- device scratch (zero-initialized at load) ----------------
__device__ __align__(16) float g_X[(long)TT * NN * KX];
__device__ __align__(16) float g_P[(long)TT * NN * G4H];
__device__ __align__(16) float g_AH[NN * KH];
__device__ __align__(16) float g_h[NN * HH];
__device__ __align__(16) float g_c[NN * HH];
__device__ float g_dinv[NN];
__device__ float g_self[NN];
__device__ __align__(16) int g_cnt[NN];
__device__ int   g_cursor[NN];
__device__ int   g_rowptr[NN + 1];
__device__ int   g_src[EE];
__device__ int   g_dst[EE];
__device__ int   g_s_src[EE];
__device__ int   g_s_eid[EE];
__device__ float g_s_gcn[EE];
__device__ __align__(16) unsigned g_Wxp_hi[(KX / 2) * G4H];
__device__ __align__(16) unsigned g_Wxp_lo[(KX / 2) * G4H];
__device__ __align__(16) unsigned g_Wgp_hi[(KH / 2) * G4H];
__device__ __align__(16) unsigned g_Wgp_lo[(KH / 2) * G4H];
__device__ __align__(16) float g_bc[G4H];
__device__ float g_colsum[TT * FF];
__device__ float g_colsq[TT * FF];
__device__ float g_mean[TT * FF];
__device__ float g_rinv[TT * FF];
__device__ float g_v[HH];
__device__ float g_raw[NN];
__device__ float g_sig[NN];
__device__ unsigned g_key[NN];
__device__ float g_high[HH];
__device__ __align__(16) float g_G[TSN * G4H];
__device__ float g_hl[HH];
__device__ unsigned g_prefix;
__device__ unsigned g_kkleft;
__device__ unsigned g_ticket;
__device__ unsigned g_cs_ticket[TT];
__device__ unsigned g_sc_ticket;
__device__ float g_ssum, g_ssq, g_smean, g_sinv, g_ploss;

__device__ __forceinline__ float sigm(float x) { return 1.f / (1.f + expf(-x)); }

// split (a,b) into packed bf16x2 hi + lo (2-term bf16 split; drops only lo*lo ~2^-18)
__device__ __forceinline__ void bf16split2(float a, float b, unsigned& hi, unsigned& lo) {
    __nv_bfloat16 ah = __float2bfloat16_rn(a);
    __nv_bfloat16 bh = __float2bfloat16_rn(b);
    float ar = a - __bfloat162float(ah);
    float br = b - __bfloat162float(bh);
    __nv_bfloat162 H; H.x = ah; H.y = bh;
    __nv_bfloat162 L; L.x = __float2bfloat16_rn(ar); L.y = __float2bfloat16_rn(br);
    hi = *(unsigned*)&H;
    lo = *(unsigned*)&L;
}

#define MMA_BF16(c0, c1, c2, c3, a0, a1, a2, a3, b0, b1)                         \
    asm volatile("mma.sync.aligned.m16n8k16.row.col.f32.bf16.bf16.f32 "          \
                 "{%0,%1,%2,%3}, {%4,%5,%6,%7}, {%8,%9}, {%0,%1,%2,%3};"         \
                 : "+f"(c0), "+f"(c1), "+f"(c2), "+f"(c3)                        \
                 : "r"(a0), "r"(a1), "r"(a2), "r"(a3), "r"(b0), "r"(b1))

// ---------------- branch B0: decode edges (+count) + copy h0/c0 ----------------
__global__ void k_decode(const void* eiraw, const float* __restrict__ h0,
                         const float* __restrict__ c0) {
    int gid = blockIdx.x * blockDim.x + threadIdx.x;   // exactly EE threads
    const long long* p64 = (const long long*)eiraw;
    bool is64 = true;
#pragma unroll
    for (int j = 0; j < 8; j++) {
        long long v = p64[j];
        if (v < 0 || v >= NN) is64 = false;
    }
    int s, d;
    if (is64) { s = (int)p64[gid]; d = (int)p64[EE + gid]; }
    else { const int* p32 = (const int*)eiraw; s = p32[gid]; d = p32[EE + gid]; }
    s = min(max(s, 0), NN - 1);
    d = min(max(d, 0), NN - 1);
    g_src[gid] = s;
    g_dst[gid] = d;
    atomicAdd(&g_cnt[d], 1);
    for (int j = gid; j < NN * HH; j += EE) { g_h[j] = h0[j]; g_c[j] = c0[j]; }
}

// ---------------- branch B1: fast single-block prefix scan + node norms ----------------
__global__ void k_prefix() {
    __shared__ int wsum[32];
    int t = threadIdx.x, lane = t & 31, wid = t >> 5;
    int vals[20];
    int s = 0;
    if (t < 1000) {
        const int4* p = (const int4*)(g_cnt + t * 20);
#pragma unroll
        for (int i = 0; i < 5; i++) {
            int4 v = p[i];
            vals[i * 4 + 0] = v.x; vals[i * 4 + 1] = v.y;
            vals[i * 4 + 2] = v.z; vals[i * 4 + 3] = v.w;
            s += v.x + v.y + v.z + v.w;
        }
    }
    int x = s;
#pragma unroll
    for (int o = 1; o < 32; o <<= 1) {
        int y = __shfl_up_sync(0xffffffffu, x, o);
        if (lane >= o) x += y;
    }
    if (lane == 31) wsum[wid] = x;
    __syncthreads();
    if (wid == 0) {
        int sv = wsum[lane];
#pragma unroll
        for (int o = 1; o < 32; o <<= 1) {
            int y = __shfl_up_sync(0xffffffffu, sv, o);
            if (lane >= o) sv += y;
        }
        wsum[lane] = sv;
    }
    __syncthreads();
    int excl = x - s + (wid > 0 ? wsum[wid - 1] : 0);
    if (t < 1000) {
        int run = excl;
#pragma unroll
        for (int j = 0; j < 20; j++) {
            int idx = t * 20 + j;
            g_rowptr[idx] = run;
            int v = vals[j];
            run += v;
            float dd = (float)v + 1.f;
            g_dinv[idx] = rsqrtf(dd);
            g_self[idx] = 1.f / dd;
            g_cnt[idx] = 0;   // reset for next replay
        }
    }
    if (t == 1023) g_rowptr[NN] = excl;   // t>=1000 have s=0, excl=total
}

// ---------------- branch B2: bucket edges by destination ----------------
__global__ void k_sortedges() {
    int e = blockIdx.x * blockDim.x + threadIdx.x;
    if (e >= EE) return;
    int s = g_src[e], d = g_dst[e];
    int pos = g_rowptr[d] + atomicAdd(&g_cursor[d], 1);
    g_s_src[pos] = s;
    g_s_eid[pos] = e;
    g_s_gcn[pos] = g_dinv[s] * g_dinv[d];
}

// ---------------- main A0: per-timestep column stats ----------------
__global__ void k_colstats(const float* __restrict__ xs) {
    __shared__ float ss[256], sq[256];
    __shared__ int islast;
    int t = blockIdx.y;
    const float* xt = xs + (long)t * NN * FF;
    int f = threadIdx.x & 63, slot = threadIdx.x >> 6;
    float s = 0.f, q = 0.f;
    for (int n = blockIdx.x * 4 + slot; n < NN; n += gridDim.x * 4) {
        float v = xt[n * 64 + f];
        s += v; q += v * v;
    }
    ss[threadIdx.x] = s; sq[threadIdx.x] = q;
    __syncthreads();
    if (slot == 0) {
        s = ss[f] + ss[f + 64] + ss[f + 128] + ss[f + 192];
        q = sq[f] + sq[f + 64] + sq[f + 128] + sq[f + 192];
        atomicAdd(&g_colsum[t * 64 + f], s);
        atomicAdd(&g_colsq[t * 64 + f], q);
    }
    __syncthreads();
    if (threadIdx.x == 0) {
        __threadfence();
        islast = (atomicAdd(&g_cs_ticket[t], 1u) == gridDim.x - 1);
    }
    __syncthreads();
    if (islast && threadIdx.x < 64) {
        int o = t * 64 + threadIdx.x;
        float fs = atomicAdd(&g_colsum[o], 0.f);
        float fq = atomicAdd(&g_colsq[o], 0.f);
        float mean = fs * (1.f / NN);
        float var = (fq - fs * fs * (1.f / NN)) * (1.f / (NN - 1));
        g_mean[o] = mean;
        g_rinv[o] = 1.f / (sqrtf(fmaxf(var, 0.f)) + 1e-6f);
        g_colsum[o] = 0.f;
        g_colsq[o] = 0.f;
        if (threadIdx.x == 0) g_cs_ticket[t] = 0u;
    }
}

// ---------------- main A1: normalize x (all T) + pack/split weights ----------------
__global__ void k_prep(const float* __restrict__ xs,
                       const float* __restrict__ Wrel, const float* __restrict__ brel,
                       const float* __restrict__ Wroot, const float* __restrict__ Wg,
                       const float* __restrict__ bg) {
    int gid = blockIdx.x * blockDim.x + threadIdx.x;   // TT*NN*FF threads
    int t = gid / (NN * FF);
    int rem = gid - t * (NN * FF);
    int n = rem >> 6, f = rem & 63;
    float xn = (xs[gid] - g_mean[t * 64 + f]) * g_rinv[t * 64 + f];
    g_X[((long)t * NN + n) * KX + 64 + f] = xn;

    if (gid < (KX / 2) * G4H) {
        int kp = gid >> 8, col = gid & 255;
        int g = col >> 6, h2 = col & 63;
        int k0 = 2 * kp, k1 = 2 * kp + 1;
        float w0 = (k0 < 64) ? Wrel[g * 4096 + k0 * 64 + h2]
                             : Wroot[g * 4096 + (k0 - 64) * 64 + h2];
        float w1 = (k1 < 64) ? Wrel[g * 4096 + k1 * 64 + h2]
                             : Wroot[g * 4096 + (k1 - 64) * 64 + h2];
        unsigned hi, lo;
        bf16split2(w0, w1, hi, lo);
        g_Wxp_hi[gid] = hi; g_Wxp_lo[gid] = lo;
    }
    if (gid < (KH / 2) * G4H) {
        int kp = gid >> 8, col = gid & 255;
        int g = col >> 6, h2 = col & 63;
        unsigned hi, lo;
        bf16split2(Wg[g * 4096 + (2 * kp) * 64 + h2],
                   Wg[g * 4096 + (2 * kp + 1) * 64 + h2], hi, lo);
        g_Wgp_hi[gid] = hi; g_Wgp_lo[gid] = lo;
    }
    if (gid < G4H) g_bc[gid] = brel[gid] + bg[gid];
}

// ---------------- main A2: batched agg_x gather (all T in one pass) ----------------
__global__ void k_xgather(const float* __restrict__ ea) {
    int node = (blockIdx.x * blockDim.x + threadIdx.x) >> 5;
    int lane = threadIdx.x & 31;
    if (node >= NN) return;
    int beg = g_rowptr[node], end = g_rowptr[node + 1];
    float2 a0 = {0.f, 0.f}, a1 = {0.f, 0.f}, a2 = {0.f, 0.f}, a3 = {0.f, 0.f};
    for (int e = beg; e < end; e++) {
        int s = g_s_src[e];
        int eid = g_s_eid[e];
        float w0 = ea[eid], w1 = ea[EE + eid], w2 = ea[2 * EE + eid], w3 = ea[3 * EE + eid];
        float2 v0 = ((const float2*)(g_X + ((long)s) * KX + 64))[lane];
        float2 v1 = ((const float2*)(g_X + ((long)(NN + s)) * KX + 64))[lane];
        float2 v2 = ((const float2*)(g_X + ((long)(2 * NN + s)) * KX + 64))[lane];
        float2 v3 = ((const float2*)(g_X + ((long)(3 * NN + s)) * KX + 64))[lane];
        a0.x += w0 * v0.x; a0.y += w0 * v0.y;
        a1.x += w1 * v1.x; a1.y += w1 * v1.y;
        a2.x += w2 * v2.x; a2.y += w2 * v2.y;
        a3.x += w3 * v3.x; a3.y += w3 * v3.y;
    }
    ((float2*)(g_X + ((long)node) * KX))[lane] = a0;
    ((float2*)(g_X + ((long)(NN + node)) * KX))[lane] = a1;
    ((float2*)(g_X + ((long)(2 * NN + node)) * KX))[lane] = a2;
    ((float2*)(g_X + ((long)(3 * NN + node)) * KX))[lane] = a3;
}

// ---------------- main A3: big batched GEMM  P = X[80000,128] @ Wx[128,256] (3xBF16) ----------------
__global__ void __launch_bounds__(256) k_biggemm() {
    __shared__ unsigned Ah[64][12], Al[64][12];
    __shared__ unsigned Bh[8][264], Bl[8][264];
    int tid = threadIdx.x;
    int lane = tid & 31, warp = tid >> 5;
    int wm = warp >> 2, wn = warp & 3;
    int gq = lane >> 2, tg = lane & 3;
    long r0 = (long)blockIdx.x * 64;

    float acc[2][4][2][4];
#pragma unroll
    for (int a = 0; a < 2; a++)
#pragma unroll
        for (int b = 0; b < 4; b++)
#pragma unroll
            for (int cc = 0; cc < 2; cc++)
#pragma unroll
                for (int d = 0; d < 4; d++) acc[a][b][cc][d] = 0.f;

    int arow = tid >> 2;
    int ac4 = (tid & 3) * 4;
    int akp = (tid & 3) * 2;
    const float* Abase = g_X + (r0 + arow) * KX + ac4;

    for (int k0 = 0; k0 < KX; k0 += BK) {
        float4 av = *(const float4*)(Abase + k0);
        unsigned h0, l0, h1, l1;
        bf16split2(av.x, av.y, h0, l0);
        bf16split2(av.z, av.w, h1, l1);
        Ah[arow][akp] = h0; Ah[arow][akp + 1] = h1;
        Al[arow][akp] = l0; Al[arow][akp + 1] = l1;
        int kp0 = (k0 >> 1);   // global packed row base
#pragma unroll
        for (int i = 0; i < 2; i++) {
            int flat4 = i * 256 + tid;            // 512 uint4 = 2048 u32
            int kpl = flat4 >> 6, c4 = (flat4 & 63) * 4;
            uint4 bh = *(const uint4*)(g_Wxp_hi + (kp0 + kpl) * G4H + c4);
            uint4 bl = *(const uint4*)(g_Wxp_lo + (kp0 + kpl) * G4H + c4);
            Bh[kpl][c4 + 0] = bh.x; Bh[kpl][c4 + 1] = bh.y;
            Bh[kpl][c4 + 2] = bh.z; Bh[kpl][c4 + 3] = bh.w;
            Bl[kpl][c4 + 0] = bl.x; Bl[kpl][c4 + 1] = bl.y;
            Bl[kpl][c4 + 2] = bl.z; Bl[kpl][c4 + 3] = bl.w;
        }
        __syncthreads();

        unsigned ahi[2][4], alo[2][4];
#pragma unroll
        for (int mi = 0; mi < 2; mi++) {
            int rb = wm * 32 + mi * 16;
            ahi[mi][0] = Ah[rb + gq][tg];     alo[mi][0] = Al[rb + gq][tg];
            ahi[mi][1] = Ah[rb + gq + 8][tg]; alo[mi][1] = Al[rb + gq + 8][tg];
            ahi[mi][2] = Ah[rb + gq][tg + 4]; alo[mi][2] = Al[rb + gq][tg + 4];
            ahi[mi][3] = Ah[rb + gq + 8][tg + 4]; alo[mi][3] = Al[rb + gq + 8][tg + 4];
        }
#pragma unroll
        for (int gg = 0; gg < 4; gg++)
#pragma unroll
            for (int s = 0; s < 2; s++) {
                int cb = gg * 64 + wn * 16 + s * 8 + gq;
                unsigned bh0 = Bh[tg][cb], bh1 = Bh[tg + 4][cb];
                unsigned bl0 = Bl[tg][cb], bl1 = Bl[tg + 4][cb];
#pragma unroll
                for (int mi = 0; mi < 2; mi++) {
                    float* C = acc[mi][gg][s];
                    MMA_BF16(C[0], C[1], C[2], C[3],
                             alo[mi][0], alo[mi][1], alo[mi][2], alo[mi][3], bh0, bh1);
                    MMA_BF16(C[0], C[1], C[2], C[3],
                             ahi[mi][0], ahi[mi][1], ahi[mi][2], ahi[mi][3], bl0, bl1);
                    MMA_BF16(C[0], C[1], C[2], C[3],
                             ahi[mi][0], ahi[mi][1], ahi[mi][2], ahi[mi][3], bh0, bh1);
                }
            }
        __syncthreads();
    }
#pragma unroll
    for (int mi = 0; mi < 2; mi++)
#pragma unroll
        for (int gg = 0; gg < 4; gg++)
#pragma unroll
            for (int s = 0; s < 2; s++)
#pragma unroll
                for (int half = 0; half < 2; half++) {
                    long row = r0 + wm * 32 + mi * 16 + gq + half * 8;
                    int j = gg * 64 + wn * 16 + s * 8 + tg * 2;
                    float2 v = make_float2(acc[mi][gg][s][half * 2 + 0],
                                           acc[mi][gg][s][half * 2 + 1]);
                    *(float2*)(g_P + row * G4H + j) = v;
                }
}

// ---------------- loop: agg_h gather ----------------
__global__ void k_hgather() {
    int node = (blockIdx.x * blockDim.x + threadIdx.x) >> 5;
    int lane = threadIdx.x & 31;
    if (node >= NN) return;
    if (lane == 0) g_cursor[node] = 0;   // reset for next replay (idempotent)
    int beg = g_rowptr[node], end = g_rowptr[node + 1];
    float slf = g_self[node];
    float2 hv = ((const float2*)(g_h + (long)node * 64))[lane];
    float2 acc = make_float2(slf * hv.x, slf * hv.y);
    for (int e = beg; e < end; e++) {
        int s = g_s_src[e];
        float gn = g_s_gcn[e];
        float2 v = ((const float2*)(g_h + (long)s * 64))[lane];
        acc.x += gn * v.x;
        acc.y += gn * v.y;
    }
    ((float2*)(g_AH + (long)node * 64))[lane] = acc;
}

// ---------------- loop: gates = AH[NN,64]@Wg + P[t] + bc, fused cell (3xBF16) ----------------
__global__ void __launch_bounds__(256) k_hgemm(int t) {
    __shared__ unsigned Ah[64][12], Al[64][12];
    __shared__ unsigned Bh[8][264], Bl[8][264];
    __shared__ float sbc[256];
    int tid = threadIdx.x;
    int lane = tid & 31, warp = tid >> 5;
    int wm = warp >> 2, wn = warp & 3;
    int gq = lane >> 2, tg = lane & 3;
    int r0 = blockIdx.x * 64;
    sbc[tid] = g_bc[tid];

    float acc[2][4][2][4];
#pragma unroll
    for (int a = 0; a < 2; a++)
#pragma unroll
        for (int b = 0; b < 4; b++)
#pragma unroll
            for (int cc = 0; cc < 2; cc++)
#pragma unroll
                for (int d = 0; d < 4; d++) acc[a][b][cc][d] = 0.f;

    int arow = tid >> 2;
    int ac4 = (tid & 3) * 4;
    int akp = (tid & 3) * 2;
    bool rowok = (r0 + arow) < NN;
    const float* Abase = g_AH + (long)(r0 + arow) * KH + ac4;

    for (int k0 = 0; k0 < KH; k0 += BK) {
        float4 av = rowok ? *(const float4*)(Abase + k0) : make_float4(0.f, 0.f, 0.f, 0.f);
        unsigned h0, l0, h1, l1;
        bf16split2(av.x, av.y, h0, l0);
        bf16split2(av.z, av.w, h1, l1);
        Ah[arow][akp] = h0; Ah[arow][akp + 1] = h1;
        Al[arow][akp] = l0; Al[arow][akp + 1] = l1;
        int kp0 = (k0 >> 1);
#pragma unroll
        for (int i = 0; i < 2; i++) {
            int flat4 = i * 256 + tid;
            int kpl = flat4 >> 6, c4 = (flat4 & 63) * 4;
            uint4 bh = *(const uint4*)(g_Wgp_hi + (kp0 + kpl) * G4H + c4);
            uint4 bl = *(const uint4*)(g_Wgp_lo + (kp0 + kpl) * G4H + c4);
            Bh[kpl][c4 + 0] = bh.x; Bh[kpl][c4 + 1] = bh.y;
            Bh[kpl][c4 + 2] = bh.z; Bh[kpl][c4 + 3] = bh.w;
            Bl[kpl][c4 + 0] = bl.x; Bl[kpl][c4 + 1] = bl.y;
            Bl[kpl][c4 + 2] = bl.z; Bl[kpl][c4 + 3] = bl.w;
        }
        __syncthreads();

        unsigned ahi[2][4], alo[2][4];
#pragma unroll
        for (int mi = 0; mi < 2; mi++) {
            int rb = wm * 32 + mi * 16;
            ahi[mi][0] = Ah[rb + gq][tg];     alo[mi][0] = Al[rb + gq][tg];
            ahi[mi][1] = Ah[rb + gq + 8][tg]; alo[mi][1] = Al[rb + gq + 8][tg];
            ahi[mi][2] = Ah[rb + gq][tg + 4]; alo[mi][2] = Al[rb + gq][tg + 4];
            ahi[mi][3] = Ah[rb + gq + 8][tg + 4]; alo[mi][3] = Al[rb + gq + 8][tg + 4];
        }
#pragma unroll
        for (int gg = 0; gg < 4; gg++)
#pragma unroll
            for (int s = 0; s < 2; s++) {
                int cb = gg * 64 + wn * 16 + s * 8 + gq;
                unsigned bh0 = Bh[tg][cb], bh1 = Bh[tg + 4][cb];
                unsigned bl0 = Bl[tg][cb], bl1 = Bl[tg + 4][cb];
#pragma unroll
                for (int mi = 0; mi < 2; mi++) {
                    float* C = acc[mi][gg][s];
                    MMA_BF16(C[0], C[1], C[2], C[3],
                             alo[mi][0], alo[mi][1], alo[mi][2], alo[mi][3], bh0, bh1);
                    MMA_BF16(C[0], C[1], C[2], C[3],
                             ahi[mi][0], ahi[mi][1], ahi[mi][2], ahi[mi][3], bl0, bl1);
                    MMA_BF16(C[0], C[1], C[2], C[3],
                             ahi[mi][0], ahi[mi][1], ahi[mi][2], ahi[mi][3], bh0, bh1);
                }
            }
        __syncthreads();
    }

    // epilogue: + P[t] + bias, LSTM cell
#pragma unroll
    for (int mi = 0; mi < 2; mi++)
#pragma unroll
        for (int s = 0; s < 2; s++)
#pragma unroll
            for (int half = 0; half < 2; half++) {
                int row = r0 + wm * 32 + mi * 16 + gq + half * 8;
                if (row >= NN) continue;
                int j = wn * 16 + s * 8 + tg * 2;
                const float* Prow = g_P + ((long)t * NN + row) * G4H;
                float2 pi = *(const float2*)(Prow + j);
                float2 pf = *(const float2*)(Prow + 64 + j);
                float2 po = *(const float2*)(Prow + 128 + j);
                float2 pm = *(const float2*)(Prow + 192 + j);
                float2 cold = *(const float2*)(g_c + (long)row * 64 + j);
                float outc[2], outh[2];
#pragma unroll
                for (int cc = 0; cc < 2; cc++) {
                    int ri = half * 2 + cc;
                    float gi = acc[mi][0][s][ri] + (cc ? pi.y : pi.x) + sbc[j + cc];
                    float gf = acc[mi][1][s][ri] + (cc ? pf.y : pf.x) + sbc[64 + j + cc];
                    float go = acc[mi][2][s][ri] + (cc ? po.y : po.x) + sbc[128 + j + cc];
                    float gm = acc[mi][3][s][ri] + (cc ? pm.y : pm.x) + sbc[192 + j + cc];
                    float ii = sigm(gi), ff = sigm(gf), oo = sigm(go);
                    float mm = fmaxf(gm, 0.f);
                    float cv = tanhf(ii * mm + ff * (cc ? cold.y : cold.x));
                    outc[cc] = cv;
                    outh[cc] = oo * tanhf(cv);
                }
                *(float2*)(g_c + (long)row * 64 + j) = make_float2(outc[0], outc[1]);
                *(float2*)(g_h + (long)row * 64 + j) = make_float2(outh[0], outh[1]);
            }
}

// ---------------- DGPool ----------------
__global__ void k_vnorm(const float* __restrict__ pv) {
    __shared__ float red[64];
    int t = threadIdx.x;
    float v = pv[t];
    red[t] = v * v;
    __syncthreads();
    for (int s = 32; s > 0; s >>= 1) { if (t < s) red[t] += red[t + s]; __syncthreads(); }
    g_v[t] = v / (sqrtf(red[0]) + 1e-8f);
}

__global__ void k_scores() {
    __shared__ float ws[8];
    __shared__ int islast;
    int lane = threadIdx.x & 31, w = threadIdx.x >> 5;
    int n = blockIdx.x * 8 + w;
    float p = 0.f;
    if (n < NN)
        p = g_h[n * 64 + lane] * g_v[lane] + g_h[n * 64 + 32 + lane] * g_v[32 + lane];
    for (int o = 16; o; o >>= 1) p += __shfl_down_sync(0xffffffffu, p, o);
    if (lane == 0) {
        if (n < NN) g_raw[n] = p;
        ws[w] = (n < NN) ? p : 0.f;
    }
    __syncthreads();
    if (threadIdx.x == 0) {
        float s = 0.f, q = 0.f;
        for (int i = 0; i < 8; i++) { s += ws[i]; q += ws[i] * ws[i]; }
        atomicAdd(&g_ssum, s);
        atomicAdd(&g_ssq, q);
        __threadfence();
        islast = (atomicAdd(&g_sc_ticket, 1u) == gridDim.x - 1);
    }
    __syncthreads();
    if (islast && threadIdx.x == 0) {
        float fs = atomicAdd(&g_ssum, 0.f);
        float fq = atomicAdd(&g_ssq, 0.f);
        float mean = fs * (1.f / NN);
        float var = fq * (1.f / NN) - mean * mean;
        g_smean = mean;
        g_sinv = 1.f / (sqrtf(fmaxf(var, 0.f)) + 1e-8f);
        g_ssum = 0.f; g_ssq = 0.f; g_sc_ticket = 0u;
    }
}

__global__ void k_standardize(float* __restrict__ out) {
    int n = blockIdx.x * blockDim.x + threadIdx.x;
    float pl = 0.f;
    if (n < NN) {
        float s = (g_raw[n] - g_smean) * g_sinv;
        out[1 + n] = s;
        float sg = sigm(s);
        g_sig[n] = sg;
        unsigned u = __float_as_uint(s);
        u = (u & 0x80000000u) ? ~u : (u | 0x80000000u);
        g_key[n] = u;
        pl = sg * (1.f - sg);
    }
    for (int o = 16; o; o >>= 1) pl += __shfl_down_sync(0xffffffffu, pl, o);
    __shared__ float sred[8];
    if ((threadIdx.x & 31) == 0) sred[threadIdx.x >> 5] = pl;
    __syncthreads();
    if (threadIdx.x == 0) {
        float s = 0.f;
        for (int i = 0; i < 8; i++) s += sred[i];
        atomicAdd(&g_ploss, s);
    }
}

// single-block 4-pass radix select: finds threshold key (prefix) + tie budget
__global__ void __launch_bounds__(1024) k_select() {
    __shared__ unsigned hist[256];
    __shared__ unsigned wsum[8];
    __shared__ unsigned s_prefix, s_kk;
    int t = threadIdx.x, lane = t & 31;
    if (t == 0) { s_prefix = 0u; s_kk = KSEL; }
#pragma unroll
    for (int pass = 0; pass < 4; pass++) {
        int shift = 24 - 8 * pass;
        if (t < 256) hist[t] = 0u;
        __syncthreads();
        unsigned pref = s_prefix;
        unsigned kk = s_kk;
        for (int i = t; i < NN; i += 1024) {
            unsigned k = g_key[i];
            bool cand = (pass == 0) || ((k >> (shift + 8)) == (pref >> (shift + 8)));
            if (cand) atomicAdd(&hist[(k >> shift) & 255u], 1u);
        }
        __syncthreads();
        unsigned x = 0, v = 0;
        if (t < 256) {
            int b = 255 - t;              // ascending t = descending bucket
            v = hist[b];
            x = v;
#pragma unroll
            for (int o = 1; o < 32; o <<= 1) {
                unsigned y = __shfl_up_sync(0xffffffffu, x, o);
                if (lane >= o) x += y;
            }
            if (lane == 31) wsum[t >> 5] = x;
        }
        __syncthreads();
        if (t < 256) {
            unsigned add = 0;
            int w = t >> 5;
            for (int j = 0; j < w; j++) add += wsum[j];
            unsigned S = x + add;          // suffix-inclusive count of buckets >= b
            unsigned Snext = S - v;        // count of buckets > b
            if (S >= kk && Snext < kk) {
                s_prefix = pref | ((unsigned)(255 - t) << shift);
                s_kk = kk - Snext;
            }
        }
        __syncthreads();
    }
    if (t == 0) { g_prefix = s_prefix; g_kkleft = s_kk; }
}

__global__ void k_sumhigh() {
    __shared__ float acc[64];
    if (threadIdx.x < 64) acc[threadIdx.x] = 0.f;
    __syncthreads();
    int lane = threadIdx.x & 31, w = threadIdx.x >> 5;
    int n = blockIdx.x * 8 + w;
    if (n < NN) {
        int inc = 0;
        if (lane == 0) {
            unsigned key = g_key[n], tau = g_prefix;
            if (key > tau) inc = 1;
            else if (key == tau) {
                unsigned tk = atomicAdd(&g_ticket, 1u);
                inc = (tk < g_kkleft) ? 1 : 0;
            }
        }
        inc = __shfl_sync(0xffffffffu, inc, 0);
        if (inc) {
            float sg = g_sig[n];
            atomicAdd(&acc[lane],      g_h[n * 64 + lane] * sg);
            atomicAdd(&acc[lane + 32], g_h[n * 64 + lane + 32] * sg);
        }
    }
    __syncthreads();
    if (threadIdx.x < 64) atomicAdd(&g_high[threadIdx.x], acc[threadIdx.x]);
}

// ---------------- branch C: raw-fMRI LSTM ----------------
__global__ void k_Ggemm(const float* __restrict__ Wih, const float* __restrict__ ts) {
    __shared__ float sW[32][65];
    __shared__ float sT[32][51];
    int r0 = blockIdx.y * 64;
    int kbeg = blockIdx.x * KCH;
    int kend = min(NN, kbeg + KCH);
    int tid = threadIdx.x;
    int r = tid & 63, tq = tid >> 6;
    float acc[13];
#pragma unroll
    for (int j = 0; j < 13; j++) acc[j] = 0.f;

    for (int k0 = kbeg; k0 < kend; k0 += 32) {
#pragma unroll
        for (int i = 0; i < 8; i++) {
            int flat = i * 256 + tid;
            int kk = flat & 31, rr = flat >> 5;
            int kg = k0 + kk;
            sW[kk][rr] = (kg < kend) ? Wih[(long)(r0 + rr) * NN + kg] : 0.f;
        }
#pragma unroll
        for (int i = 0; i < 7; i++) {
            int flat = i * 256 + tid;
            if (flat < 1600) {
                int kk = flat & 31, t = flat >> 5;
                int kg = k0 + kk;
                sT[kk][t] = (kg < kend) ? ts[(long)t * NN + kg] : 0.f;
            }
        }
        __syncthreads();
#pragma unroll
        for (int kk = 0; kk < 32; kk++) {
            float wv = sW[kk][r];
#pragma unroll
            for (int j = 0; j < 13; j++) {
                int t = tq + 4 * j;
                if (t < TSN) acc[j] += wv * sT[kk][t];
            }
        }
        __syncthreads();
    }
#pragma unroll
    for (int j = 0; j < 13; j++) {
        int t = tq + 4 * j;
        if (t < TSN) atomicAdd(&g_G[t * G4H + r0 + r], acc[j]);
    }
}

__global__ void k_lstm(const float* __restrict__ Whh, const float* __restrict__ bih,
                       const float* __restrict__ bhh) {
    __shared__ float sh[64], scc[64], sg[256];
    int r = threadIdx.x;
    float wr[64];
#pragma unroll
    for (int m = 0; m < 64; m++) wr[m] = Whh[r * 64 + m];
    float bias = bih[r] + bhh[r];
    if (r < 64) { sh[r] = 0.f; scc[r] = 0.f; }
    __syncthreads();
    for (int t = 0; t < TSN; t++) {
        float a0 = 0.f, a1 = 0.f, a2 = 0.f, a3 = 0.f;
#pragma unroll
        for (int m = 0; m < 64; m += 4) {
            a0 += wr[m] * sh[m];
            a1 += wr[m + 1] * sh[m + 1];
            a2 += wr[m + 2] * sh[m + 2];
            a3 += wr[m + 3] * sh[m + 3];
        }
        float gv = g_G[t * G4H + r];
        g_G[t * G4H + r] = 0.f;   // reset for next replay
        sg[r] = gv + bias + ((a0 + a1) + (a2 + a3));
        __syncthreads();
        if (r < 64) {
            float gi = sg[r], gf = sg[64 + r], gg = sg[128 + r], go = sg[192 + r];
            float c = sigm(gf) * scc[r] + sigm(gi) * tanhf(gg);
            scc[r] = c;
            sh[r] = sigm(go) * tanhf(c);
        }
        __syncthreads();
    }
    if (r < 64) g_hl[r] = sh[r];
}

// ---------------- fusion head (+global resets for next replay) ----------------
__global__ void k_final(const float* __restrict__ lng, const float* __restrict__ lnb,
                        const float* __restrict__ W1, const float* __restrict__ b1,
                        const float* __restrict__ W2, const float* __restrict__ b2,
                        float* __restrict__ out) {
    __shared__ float red[128], sf[128], sz[64];
    int tid = threadIdx.x;
    float x = (tid < 64) ? g_high[tid] * (1.f / KSEL) : g_hl[tid - 64];
    if (tid < 64) g_high[tid] = 0.f;    // reset
    red[tid] = x;
    __syncthreads();
    for (int s = 64; s > 0; s >>= 1) { if (tid < s) red[tid] += red[tid + s]; __syncthreads(); }
    float mean = red[0] * (1.f / 128.f);
    __syncthreads();
    float d = x - mean;
    red[tid] = d * d;
    __syncthreads();
    for (int s = 64; s > 0; s >>= 1) { if (tid < s) red[tid] += red[tid + s]; __syncthreads(); }
    float var = red[0] * (1.f / 128.f);
    float y = d * rsqrtf(var + 1e-5f) * lng[tid] + lnb[tid];
    __syncthreads();
    sf[tid] = y;
    __syncthreads();
    if (tid < 64) {
        float a = b1[tid];
        for (int j = 0; j < 128; j++) a += sf[j] * W1[j * 64 + tid];
        sz[tid] = fmaxf(a, 0.f);
    }
    __syncthreads();
    red[tid] = (tid < 64) ? sz[tid] * W2[tid] : 0.f;
    __syncthreads();
    for (int s = 64; s > 0; s >>= 1) { if (tid < s) red[tid] += red[tid + s]; __syncthreads(); }
    if (tid == 0) {
        out[0] = red[0] + b2[0];
        out[NN + 1] = g_ploss * (1.f / NN);
        g_ploss = 0.f;
        g_ticket = 0u;
    }
}

// ---------------- launch (forked graph; streams/events created ONCE) ----------------
extern "C" void kernel_launch(void* const* d_in, const int* in_sizes, int n_in,
                              void* d_out, int out_size) {
    const float* xs   = (const float*)d_in[0];
    const void*  ei   = d_in[1];
    const float* ea   = (const float*)d_in[2];
    const float* h0   = (const float*)d_in[3];
    const float* c0   = (const float*)d_in[4];
    const float* ts   = (const float*)d_in[5];
    const float* Wrel = (const float*)d_in[6];
    const float* brel = (const float*)d_in[7];
    const float* Wroot= (const float*)d_in[8];
    const float* Wg   = (const float*)d_in[9];
    const float* bg   = (const float*)d_in[10];
    const float* pool = (const float*)d_in[11];
    const float* lng  = (const float*)d_in[12];
    const float* lnb  = (const float*)d_in[13];
    const float* Wih  = (const float*)d_in[14];
    const float* Whh  = (const float*)d_in[15];
    const float* bih  = (const float*)d_in[16];
    const float* bhh  = (const float*)d_in[17];
    const float* W1   = (const float*)d_in[18];
    const float* b1   = (const float*)d_in[19];
    const float* W2   = (const float*)d_in[20];
    const float* b2   = (const float*)d_in[21];
    float* out = (float*)d_out;

    // Created once on the first (correctness) call — before the harness's
    // pre-capture baseline — reused thereafter; nothing allocated in capture.
    static cudaStream_t sB = nullptr, sC = nullptr;
    static cudaEvent_t evFork = nullptr, evEdges = nullptr, evLstm = nullptr, evV = nullptr;
    if (sB == nullptr) {
        cudaStreamCreateWithFlags(&sB, cudaStreamNonBlocking);
        cudaStreamCreateWithFlags(&sC, cudaStreamNonBlocking);
        cudaEventCreateWithFlags(&evFork, cudaEventDisableTiming);
        cudaEventCreateWithFlags(&evEdges, cudaEventDisableTiming);
        cudaEventCreateWithFlags(&evLstm, cudaEventDisableTiming);
        cudaEventCreateWithFlags(&evV, cudaEventDisableTiming);
    }

    cudaEventRecord(evFork, 0);
    cudaStreamWaitEvent(sB, evFork, 0);
    cudaStreamWaitEvent(sC, evFork, 0);

    // branch B: edge structure + h/c init
    k_decode<<<EE / 256, 256, 0, sB>>>(ei, h0, c0);
    k_prefix<<<1, 1024, 0, sB>>>();
    k_sortedges<<<EE / 256, 256, 0, sB>>>();
    cudaEventRecord(evEdges, sB);

    // branch C: pool-vec norm + fMRI LSTM (independent of main until scores/final)
    k_vnorm<<<1, 64, 0, sC>>>(pool);
    cudaEventRecord(evV, sC);
    k_Ggemm<<<dim3(128, 4), 256, 0, sC>>>(Wih, ts);
    k_lstm<<<1, 256, 0, sC>>>(Whh, bih, bhh);
    cudaEventRecord(evLstm, sC);

    // main branch
    k_colstats<<<dim3(40, TT), 256>>>(xs);
    k_prep<<<(TT * NN * FF) / 256, 256>>>(xs, Wrel, brel, Wroot, Wg, bg);
    cudaStreamWaitEvent(0, evEdges, 0);
    k_xgather<<<(NN * 32 + 255) / 256, 256>>>(ea);
    k_biggemm<<<(TT * NN) / 64, 256>>>();

    for (int t = 0; t < TT; t++) {
        k_hgather<<<(NN * 32 + 255) / 256, 256>>>();
        k_hgemm<<<(NN + 63) / 64, 256>>>(t);
    }

    cudaStreamWaitEvent(0, evV, 0);
    k_scores<<<(NN + 7) / 8, 256>>>();
    k_standardize<<<(NN + 255) / 256, 256>>>(out);
    k_select<<<1, 1024>>>();
    k_sumhigh<<<(NN + 7) / 8, 256>>>();

    cudaStreamWaitEvent(0, evLstm, 0);
    k_final<<<1, 128>>>(lng, lnb, W1, b1, W2, b2, out);
}